// round 5
// baseline (speedup 1.0000x reference)
#include <cuda_runtime.h>
#include <math.h>
#include <stdint.h>

#define Bsz 8
#define Ssz 1024
#define Dsz 512
#define Hsz 8
#define DHsz 64
#define FFsz 1024
#define NPOS 64          // 2*SPAN
#define NROWS (Bsz*Ssz)  // 8192

// ---------------- scratch (device globals; no allocation allowed) ------------
__device__ float g_xn  [Bsz*Ssz*Dsz];
__device__ float g_conv[Bsz*Ssz*Dsz];
__device__ float g_x1  [Bsz*Ssz*Dsz];
__device__ float g_x2  [Bsz*Ssz*Dsz];
__device__ float g_q   [Bsz*Ssz*Dsz];
__device__ float g_k   [Bsz*Ssz*Dsz];
__device__ float g_v   [Bsz*Ssz*Dsz];
__device__ float g_vt  [Bsz*Ssz*Dsz];   // [B, D, S]
__device__ float g_ctx [Bsz*Ssz*Dsz];
__device__ float g_posk[NPOS*Dsz];
__device__ float g_posq[NPOS*Dsz];
__device__ float g_c2p [Bsz*Hsz*Ssz*NPOS];
__device__ float g_p2c [Bsz*Hsz*Ssz*NPOS];
__device__ float g_ff  [Bsz*Ssz*FFsz];
__device__ int   g_lut [2*Ssz];

// ---------------- relative-position bucket LUT --------------------------------
__global__ void build_lut_kernel(int* __restrict__ lut) {
    int t = blockIdx.x * blockDim.x + threadIdx.x;
    if (t >= 2*Ssz - 1) return;
    int rel = t - (Ssz - 1);   // i - j
    const int mid = 16;        // BUCKETS/2
    int bucket;
    if (rel > -mid && rel < mid) {
        bucket = rel;
    } else {
        float absp = fabsf((float)rel);
        if (absp <= (float)mid) {
            bucket = rel;
        } else {
            float logp = ceilf(logf(absp / 16.0f) / logf(127.0f / 16.0f) * 15.0f) + 16.0f;
            bucket = (rel > 0 ? 1 : -1) * (int)logp;
        }
    }
    int idx = bucket + 32;
    idx = min(max(idx, 0), 63);
    lut[t] = idx;
}

// ---------------- LayerNorm (D=512, one block per row) ------------------------
__global__ void layernorm_kernel(const float* __restrict__ x,
                                 const float* __restrict__ g,
                                 const float* __restrict__ bb,
                                 float* __restrict__ out) {
    const float* xr = x + (size_t)blockIdx.x * Dsz;
    float* orow = out + (size_t)blockIdx.x * Dsz;
    int tid = threadIdx.x;  // 256
    float v0 = xr[tid], v1 = xr[tid + 256];
    float s = v0 + v1, ss = v0 * v0 + v1 * v1;
    __shared__ float r1[8], r2[8];
    #pragma unroll
    for (int o = 16; o; o >>= 1) {
        s  += __shfl_xor_sync(0xffffffffu, s, o);
        ss += __shfl_xor_sync(0xffffffffu, ss, o);
    }
    if ((tid & 31) == 0) { r1[tid >> 5] = s; r2[tid >> 5] = ss; }
    __syncthreads();
    float S1 = 0.f, S2 = 0.f;
    #pragma unroll
    for (int i = 0; i < 8; i++) { S1 += r1[i]; S2 += r2[i]; }
    float mean = S1 * (1.0f / Dsz);
    float var  = S2 * (1.0f / Dsz) - mean * mean;
    float rs = rsqrtf(var + 1e-5f);
    orow[tid]       = (v0 - mean) * rs * g[tid]       + bb[tid];
    orow[tid + 256] = (v1 - mean) * rs * g[tid + 256] + bb[tid + 256];
}

// ---------------- depthwise conv (K=3 along S) + bias + SiLU ------------------
__global__ void dwconv_silu_kernel(const float* __restrict__ xn,
                                   const float* __restrict__ w,
                                   const float* __restrict__ bias,
                                   float* __restrict__ out) {
    size_t idx = (size_t)blockIdx.x * blockDim.x + threadIdx.x;
    if (idx >= (size_t)Bsz * Ssz * Dsz) return;
    int d = (int)(idx % Dsz);
    int s = (int)((idx / Dsz) % Ssz);
    const float* base = xn + idx;
    float w0 = w[d * 3 + 0], w1 = w[d * 3 + 1], w2 = w[d * 3 + 2];
    float acc = bias[d] + base[0] * w1;
    if (s > 0)        acc += base[-Dsz] * w0;
    if (s < Ssz - 1)  acc += base[ Dsz] * w2;
    out[idx] = acc / (1.0f + expf(-acc));  // silu
}

// ---------------- V transpose: [B,S,D] -> [B,D,S] ------------------------------
__global__ void transpose_v_kernel(const float* __restrict__ v, float* __restrict__ vt) {
    __shared__ float tile[32][33];
    int b = blockIdx.z;
    int s0 = blockIdx.x * 32, d0 = blockIdx.y * 32;
    int tx = threadIdx.x, ty = threadIdx.y;  // 32 x 8
    #pragma unroll
    for (int j = 0; j < 32; j += 8)
        tile[ty + j][tx] = v[((size_t)b * Ssz + s0 + ty + j) * Dsz + d0 + tx];
    __syncthreads();
    #pragma unroll
    for (int j = 0; j < 32; j += 8)
        vt[((size_t)b * Dsz + d0 + ty + j) * Ssz + s0 + tx] = tile[tx][ty + j];
}

// ---------------- mma.tf32 + ldmatrix helpers ----------------------------------
__device__ __forceinline__ void mma_tf32(float c[4], const uint32_t a[4], const uint32_t b[2]) {
    asm volatile(
        "mma.sync.aligned.m16n8k8.row.col.f32.tf32.tf32.f32 "
        "{%0,%1,%2,%3}, {%4,%5,%6,%7}, {%8,%9}, {%0,%1,%2,%3};"
        : "+f"(c[0]), "+f"(c[1]), "+f"(c[2]), "+f"(c[3])
        : "r"(a[0]), "r"(a[1]), "r"(a[2]), "r"(a[3]), "r"(b[0]), "r"(b[1]));
}

__device__ __forceinline__ void ldsm_x4(uint32_t r[4], uint32_t addr) {
    asm volatile("ldmatrix.sync.aligned.m8n8.x4.shared.b16 {%0,%1,%2,%3}, [%4];"
                 : "=r"(r[0]), "=r"(r[1]), "=r"(r[2]), "=r"(r[3]) : "r"(addr));
}

#define CP_ASYNC16(dst_u32, src_ptr) \
    asm volatile("cp.async.ca.shared.global [%0], [%1], 16;" :: "r"(dst_u32), "l"(src_ptr))
#define CP_COMMIT() asm volatile("cp.async.commit_group;")
#define CP_WAIT2()  asm volatile("cp.async.wait_group 2;")
#define CP_WAIT1()  asm volatile("cp.async.wait_group 1;")
#define CP_WAIT0()  asm volatile("cp.async.wait_group 0;")

// ---------------- tensor-core TN GEMM (128x64 tiles, 3-stage, 1 barrier/iter) --
// C[m,n] = sum_k A[m,k] * W[n,k]
// EPI: 0 none, 1 +bias, 2 +bias+res, 3 silu(+bias)
// MODE: 0 plain, 3 pos-merged (z<64: q.posk -> c2p ; z>=64: k.posq -> p2c),
//       4 qkv-merged (z selects {qw,kw,vw})
#define SSTRIDE 20
#define CN 64

template<int EPI, int MODE>
__global__ void __launch_bounds__(256, 3) gemm_mma_kernel(
    const float* __restrict__ A0, int lda,
    const float* __restrict__ W0, int ldw,
    const float* __restrict__ bias0, const float* __restrict__ res,
    float* __restrict__ C0, int ldc, int K,
    const float* __restrict__ Aa, const float* __restrict__ Wa,
    const float* __restrict__ Wb2, const float* __restrict__ ba,
    const float* __restrict__ bb2, float* __restrict__ Ca, float* __restrict__ Cb)
{
    // 8 warps: 4 along M (32 rows each), 2 along N (32 cols each)
    __shared__ float As[3][128 * SSTRIDE];
    __shared__ float Ws[3][CN  * SSTRIDE];

    const int tid  = threadIdx.x;
    const int wid  = tid >> 5, lane = tid & 31;
    const int g    = lane >> 2, tg = lane & 3;
    const int wm   = wid & 3, wn = wid >> 2;

    const int z = blockIdx.z;
    const float* A = A0; const float* W = W0; float* C = C0;
    const float* bias = bias0;
    if (MODE == 3) {
        int zz = z & 63, sel = z >> 6;
        int bb = zz >> 3, hh = zz & 7;
        A = (sel ? Aa : A0) + (size_t)bb * Ssz * Dsz + hh * DHsz;
        W = (sel ? Wa : W0) + hh * DHsz;
        C = (sel ? Ca : C0) + (size_t)zz * Ssz * NPOS;
    } else if (MODE == 4) {
        W    = (z == 0) ? W0 : (z == 1 ? Wa : Wb2);
        bias = (z == 0) ? bias0 : (z == 1 ? ba : bb2);
        C    = (z == 0) ? C0 : (z == 1 ? Ca : Cb);
    }

    const int m_cta = blockIdx.y * 128, n_cta = blockIdx.x * CN;

    const uint32_t sA = (uint32_t)__cvta_generic_to_shared(&As[0][0]);
    const uint32_t sW = (uint32_t)__cvta_generic_to_shared(&Ws[0][0]);

    const int qd = (tid & 3) * 4;
    const int rr = tid >> 2;

    auto fetch = [&](int t, int buf) {
        int k0 = t * 16;
        #pragma unroll
        for (int r = 0; r < 2; r++) {
            int row = rr + 64 * r;
            uint32_t d = sA + (uint32_t)(buf * 128 * SSTRIDE + row * SSTRIDE + qd) * 4u;
            CP_ASYNC16(d, A + (size_t)(m_cta + row) * lda + k0 + qd);
        }
        {
            uint32_t d = sW + (uint32_t)(buf * CN * SSTRIDE + rr * SSTRIDE + qd) * 4u;
            CP_ASYNC16(d, W + (size_t)(n_cta + rr) * ldw + k0 + qd);
        }
        CP_COMMIT();
    };

    // ldmatrix per-thread offsets (float units)
    const int lq = lane >> 3, lr = lane & 7;
    const int aoff = ((lq & 1) * 8 + lr) * SSTRIDE + (lq >> 1) * 4;  // A frag
    const int boff = ((lq >> 1) * 8 + lr) * SSTRIDE + (lq & 1) * 4;  // B frag pair

    float acc[2][4][4] = {};

    const int T = K / 16;
    fetch(0, 0);
    fetch(1, 1);
    for (int it = 0; it < T; it++) {
        const int buf = it % 3;
        CP_WAIT1();          // stage `it` resident
        __syncthreads();     // all warps done with stage it-1's buffer
        if (it + 2 < T) fetch(it + 2, (it + 2) % 3);

        const uint32_t bA = sA + (uint32_t)(buf * 128 * SSTRIDE) * 4u;
        const uint32_t bW = sW + (uint32_t)(buf * CN  * SSTRIDE) * 4u;

        uint32_t af[2][2][4];   // [ks][im][4]
        uint32_t bf[2][2][4];   // [ks][pair][4]
        #pragma unroll
        for (int ks = 0; ks < 2; ks++) {
            const int kk = ks * 8;
            #pragma unroll
            for (int im = 0; im < 2; im++)
                ldsm_x4(af[ks][im], bA + (uint32_t)((wm * 32 + im * 16) * SSTRIDE + aoff + kk) * 4u);
            #pragma unroll
            for (int ip = 0; ip < 2; ip++)
                ldsm_x4(bf[ks][ip], bW + (uint32_t)((wn * 32 + ip * 16) * SSTRIDE + boff + kk) * 4u);
        }
        #pragma unroll
        for (int ks = 0; ks < 2; ks++)
            #pragma unroll
            for (int im = 0; im < 2; im++)
                #pragma unroll
                for (int in = 0; in < 4; in++)
                    mma_tf32(acc[im][in], af[ks][im], &bf[ks][in >> 1][(in & 1) * 2]);
    }

    #pragma unroll
    for (int im = 0; im < 2; im++) {
        int mrow0 = m_cta + wm * 32 + im * 16 + g;
        #pragma unroll
        for (int in = 0; in < 4; in++) {
            int ncol0 = n_cta + wn * 32 + in * 8 + tg * 2;
            #pragma unroll
            for (int e = 0; e < 4; e++) {
                int m = mrow0 + ((e >= 2) ? 8 : 0);
                int n = ncol0 + (e & 1);
                float vv = acc[im][in][e];
                if (EPI == 1 || EPI == 2 || EPI == 3) vv += bias[n];
                if (EPI == 2) vv += res[(size_t)m * ldc + n];
                if (EPI == 3) vv = vv / (1.0f + expf(-vv));
                C[(size_t)m * ldc + n] = vv;
            }
        }
    }
}

// ---------------- small SIMT GEMM (pos projections, M=64) ---------------------
#define TK 16
#define TPAD 68
__global__ void gemm_tn_small_kernel(const float* __restrict__ A, int lda,
                                     const float* __restrict__ W, int ldw,
                                     const float* __restrict__ bias,
                                     float* __restrict__ C, int ldc, int Kd) {
    int m0 = blockIdx.y * 64, n0 = blockIdx.x * 64;
    __shared__ float As[TK][TPAD];
    __shared__ float Ws2[TK][TPAD];
    const int tid = threadIdx.x;
    const int tx = tid & 15, ty = tid >> 4;
    const int lk = tid & 15, lm = tid >> 4;
    float acc[4][4] = {};
    for (int k0 = 0; k0 < Kd; k0 += TK) {
        #pragma unroll
        for (int r = 0; r < 4; r++) {
            As[lk][lm + 16 * r]  = A[(size_t)(m0 + lm + 16 * r) * lda + k0 + lk];
            Ws2[lk][lm + 16 * r] = W[(size_t)(n0 + lm + 16 * r) * ldw + k0 + lk];
        }
        __syncthreads();
        #pragma unroll
        for (int kk = 0; kk < TK; kk++) {
            float4 a = *(const float4*)&As[kk][ty * 4];
            float4 b = *(const float4*)&Ws2[kk][tx * 4];
            float av[4] = {a.x, a.y, a.z, a.w};
            float bv[4] = {b.x, b.y, b.z, b.w};
            #pragma unroll
            for (int i = 0; i < 4; i++)
                #pragma unroll
                for (int j = 0; j < 4; j++)
                    acc[i][j] += av[i] * bv[j];
        }
        __syncthreads();
    }
    #pragma unroll
    for (int i = 0; i < 4; i++) {
        int m = m0 + ty * 4 + i;
        #pragma unroll
        for (int j = 0; j < 4; j++) {
            int n = n0 + tx * 4 + j;
            C[(size_t)m * ldc + n] = acc[i][j] + bias[n];
        }
    }
}

// =========================== fused flash attention =============================
// One CTA per (z = b*H+h, i-tile of 128). 8 warps; warp w owns rows [w*16, w*16+16).
#define KST 68
#define PST 132
#define FA_SMEM ((128*KST + 64*PST + 128*PST) * 4)

__global__ void __launch_bounds__(256, 1) flash_attn_kernel(
    const float* __restrict__ qg, const float* __restrict__ kg,
    const float* __restrict__ vt,
    const float* __restrict__ c2p, const float* __restrict__ p2c,
    const int* __restrict__ lut, float* __restrict__ ctx)
{
    extern __shared__ float sm[];
    float* Kb = sm;                        // 128 x 68
    float* Vb = sm + 128*KST;              // 64 x 132
    float* Pb = sm + 128*KST + 64*PST;     // 128 x 132 (and Q stage @ stride 68)

    const int tid = threadIdx.x, w = tid >> 5, lane = tid & 31;
    const int g = lane >> 2, tg = lane & 3;
    const int z = blockIdx.z, bb = z >> 3, hh = z & 7;
    const int i0 = blockIdx.x * 128;

    const float* c2pz = c2p + (size_t)z * Ssz * NPOS;
    const float* p2cz = p2c + (size_t)z * Ssz * NPOS;

    const uint32_t sK = (uint32_t)__cvta_generic_to_shared(Kb);
    const uint32_t sV = (uint32_t)__cvta_generic_to_shared(Vb);
    const uint32_t sP = (uint32_t)__cvta_generic_to_shared(Pb);

    auto loadK = [&](int jt) {
        int j0 = jt * 128;
        #pragma unroll
        for (int c = 0; c < 8; c++) {
            int id = tid * 8 + c;
            int row = id >> 4, fcol = (id & 15) * 4;
            CP_ASYNC16(sK + (uint32_t)(row * KST + fcol) * 4u,
                       kg + ((size_t)bb * Ssz + j0 + row) * Dsz + hh * DHsz + fcol);
        }
        CP_COMMIT();
    };
    auto loadV = [&](int jt) {
        int j0 = jt * 128;
        #pragma unroll
        for (int c = 0; c < 8; c++) {
            int id = tid * 8 + c;
            int row = id >> 5, fcol = (id & 31) * 4;
            CP_ASYNC16(sV + (uint32_t)(row * PST + fcol) * 4u,
                       vt + ((size_t)bb * Dsz + hh * DHsz + row) * Ssz + j0 + fcol);
        }
        CP_COMMIT();
    };

    #pragma unroll
    for (int c = 0; c < 8; c++) {
        int id = tid * 8 + c;
        int row = id >> 4, fcol = (id & 15) * 4;
        CP_ASYNC16(sP + (uint32_t)(row * KST + fcol) * 4u,
                   qg + ((size_t)bb * Ssz + i0 + row) * Dsz + hh * DHsz + fcol);
    }
    CP_COMMIT();
    loadK(0);
    loadV(0);

    CP_WAIT2();          // Q done
    __syncthreads();

    const int lq = lane >> 3, lr = lane & 7;
    const int aoffQ = ((lq & 1) * 8 + lr) * KST + (lq >> 1) * 4;
    const int boffK = ((lq >> 1) * 8 + lr) * KST + (lq & 1) * 4;
    const int aoffP = ((lq & 1) * 8 + lr) * PST + (lq >> 1) * 4;
    const int boffV = ((lq >> 1) * 8 + lr) * PST + (lq & 1) * 4;

    uint32_t qf[8][4];
    #pragma unroll
    for (int kc = 0; kc < 8; kc++)
        ldsm_x4(qf[kc], sP + (uint32_t)((w * 16) * KST + aoffQ + kc * 8) * 4u);

    float acc_o[8][4] = {};
    float m_r[2] = {-1e30f, -1e30f};
    float l_r[2] = {0.f, 0.f};
    const float SCALE = 0.07216878364870323f;  // 1/sqrt(64*3)
    const int mg0 = i0 + w * 16 + g;

    for (int jt = 0; jt < 8; jt++) {
        const int j0 = jt * 128;
        CP_WAIT1();          // K_jt arrived
        __syncthreads();

        // ---- S = Q K^T ----
        float acc_s[16][4] = {};
        #pragma unroll
        for (int kc = 0; kc < 8; kc++) {
            #pragma unroll
            for (int ip = 0; ip < 8; ip++) {
                uint32_t bf[4];
                ldsm_x4(bf, sK + (uint32_t)((ip * 16) * KST + boffK + kc * 8) * 4u);
                mma_tf32(acc_s[ip * 2],     qf[kc], &bf[0]);
                mma_tf32(acc_s[ip * 2 + 1], qf[kc], &bf[2]);
            }
        }

        // ---- bias + online softmax ----
        float mx0 = -1e30f, mx1 = -1e30f;
        #pragma unroll
        for (int in = 0; in < 16; in++) {
            int nbase = j0 + in * 8 + tg * 2;
            #pragma unroll
            for (int e = 0; e < 4; e++) {
                int m = mg0 + ((e >= 2) ? 8 : 0);
                int n = nbase + (e & 1);
                int idx = __ldg(&lut[m - n + (Ssz - 1)]);
                float vv = (acc_s[in][e] + __ldg(&c2pz[(size_t)m * NPOS + idx])
                                         + __ldg(&p2cz[(size_t)n * NPOS + idx])) * SCALE;
                acc_s[in][e] = vv;
                if (e < 2) mx0 = fmaxf(mx0, vv); else mx1 = fmaxf(mx1, vv);
            }
        }
        mx0 = fmaxf(mx0, __shfl_xor_sync(0xffffffffu, mx0, 1));
        mx0 = fmaxf(mx0, __shfl_xor_sync(0xffffffffu, mx0, 2));
        mx1 = fmaxf(mx1, __shfl_xor_sync(0xffffffffu, mx1, 1));
        mx1 = fmaxf(mx1, __shfl_xor_sync(0xffffffffu, mx1, 2));
        float mn0 = fmaxf(m_r[0], mx0), mn1 = fmaxf(m_r[1], mx1);
        float al0 = __expf(m_r[0] - mn0), al1 = __expf(m_r[1] - mn1);
        float s0 = 0.f, s1 = 0.f;
        #pragma unroll
        for (int in = 0; in < 16; in++) {
            float p0 = __expf(acc_s[in][0] - mn0);
            float p1 = __expf(acc_s[in][1] - mn0);
            float p2 = __expf(acc_s[in][2] - mn1);
            float p3 = __expf(acc_s[in][3] - mn1);
            acc_s[in][0] = p0; acc_s[in][1] = p1; acc_s[in][2] = p2; acc_s[in][3] = p3;
            s0 += p0 + p1; s1 += p2 + p3;
        }
        l_r[0] = l_r[0] * al0 + s0;
        l_r[1] = l_r[1] * al1 + s1;
        m_r[0] = mn0; m_r[1] = mn1;
        #pragma unroll
        for (int nf = 0; nf < 8; nf++) {
            acc_o[nf][0] *= al0; acc_o[nf][1] *= al0;
            acc_o[nf][2] *= al1; acc_o[nf][3] *= al1;
        }

        __syncthreads();
        if (jt < 7) loadK(jt + 1);

        // ---- store P ----
        #pragma unroll
        for (int in = 0; in < 16; in++) {
            int col = in * 8 + tg * 2;
            *(float2*)&Pb[(w * 16 + g)     * PST + col] = make_float2(acc_s[in][0], acc_s[in][1]);
            *(float2*)&Pb[(w * 16 + g + 8) * PST + col] = make_float2(acc_s[in][2], acc_s[in][3]);
        }
        if (jt < 7) { CP_WAIT1(); } else { CP_WAIT0(); }  // V_jt arrived
        __syncthreads();

        // ---- O += P V ----
        #pragma unroll
        for (int kc2 = 0; kc2 < 16; kc2++) {
            uint32_t af[4];
            ldsm_x4(af, sP + (uint32_t)((w * 16) * PST + aoffP + kc2 * 8) * 4u);
            #pragma unroll
            for (int ip = 0; ip < 4; ip++) {
                uint32_t bf[4];
                ldsm_x4(bf, sV + (uint32_t)((ip * 16) * PST + boffV + kc2 * 8) * 4u);
                mma_tf32(acc_o[ip * 2],     af, &bf[0]);
                mma_tf32(acc_o[ip * 2 + 1], af, &bf[2]);
            }
        }
        __syncthreads();
        if (jt < 7) loadV(jt + 1);
    }

    // ---- finalize ----
    float l0 = l_r[0];
    l0 += __shfl_xor_sync(0xffffffffu, l0, 1);
    l0 += __shfl_xor_sync(0xffffffffu, l0, 2);
    float l1 = l_r[1];
    l1 += __shfl_xor_sync(0xffffffffu, l1, 1);
    l1 += __shfl_xor_sync(0xffffffffu, l1, 2);
    float inv0 = 1.0f / l0, inv1 = 1.0f / l1;
    float* c0 = ctx + ((size_t)bb * Ssz + mg0)     * Dsz + hh * DHsz;
    float* c1 = ctx + ((size_t)bb * Ssz + mg0 + 8) * Dsz + hh * DHsz;
    #pragma unroll
    for (int nf = 0; nf < 8; nf++) {
        int col = nf * 8 + tg * 2;
        *(float2*)&c0[col] = make_float2(acc_o[nf][0] * inv0, acc_o[nf][1] * inv0);
        *(float2*)&c1[col] = make_float2(acc_o[nf][2] * inv1, acc_o[nf][3] * inv1);
    }
}

// =============================== launch ========================================
extern "C" void kernel_launch(void* const* d_in, const int* in_sizes, int n_in,
                              void* d_out, int out_size) {
    const float* x      = (const float*)d_in[0];
    const float* ln1g   = (const float*)d_in[1];
    const float* ln1b   = (const float*)d_in[2];
    const float* dww    = (const float*)d_in[3];
    const float* dwb    = (const float*)d_in[4];
    const float* pww    = (const float*)d_in[5];
    const float* pwb    = (const float*)d_in[6];
    const float* ln2g   = (const float*)d_in[7];
    const float* ln2b   = (const float*)d_in[8];
    const float* qw     = (const float*)d_in[9];
    const float* qb     = (const float*)d_in[10];
    const float* kw     = (const float*)d_in[11];
    const float* kb     = (const float*)d_in[12];
    const float* vw     = (const float*)d_in[13];
    const float* vb     = (const float*)d_in[14];
    const float* ow     = (const float*)d_in[15];
    const float* ob     = (const float*)d_in[16];
    const float* relemb = (const float*)d_in[17];
    const float* ln3g   = (const float*)d_in[18];
    const float* ln3b   = (const float*)d_in[19];
    const float* w1     = (const float*)d_in[20];
    const float* b1     = (const float*)d_in[21];
    const float* w2     = (const float*)d_in[22];
    const float* b2     = (const float*)d_in[23];
    float* out = (float*)d_out;

    float *xn, *conv, *x1, *x2, *q, *k, *v, *vt, *ctx, *posk, *posq, *c2p, *p2c, *ff;
    int* lut;
    cudaGetSymbolAddress((void**)&xn,   g_xn);
    cudaGetSymbolAddress((void**)&conv, g_conv);
    cudaGetSymbolAddress((void**)&x1,   g_x1);
    cudaGetSymbolAddress((void**)&x2,   g_x2);
    cudaGetSymbolAddress((void**)&q,    g_q);
    cudaGetSymbolAddress((void**)&k,    g_k);
    cudaGetSymbolAddress((void**)&v,    g_v);
    cudaGetSymbolAddress((void**)&vt,   g_vt);
    cudaGetSymbolAddress((void**)&ctx,  g_ctx);
    cudaGetSymbolAddress((void**)&posk, g_posk);
    cudaGetSymbolAddress((void**)&posq, g_posq);
    cudaGetSymbolAddress((void**)&c2p,  g_c2p);
    cudaGetSymbolAddress((void**)&p2c,  g_p2c);
    cudaGetSymbolAddress((void**)&ff,   g_ff);
    cudaGetSymbolAddress((void**)&lut,  g_lut);

    static int smem_set = 0;
    if (!smem_set) {
        cudaFuncSetAttribute(flash_attn_kernel,
                             cudaFuncAttributeMaxDynamicSharedMemorySize, FA_SMEM);
        smem_set = 1;
    }

    build_lut_kernel<<<8, 256>>>(lut);

    // ---- conv block ----
    layernorm_kernel<<<NROWS, 256>>>(x, ln1g, ln1b, xn);
    dwconv_silu_kernel<<<(Bsz*Ssz*Dsz + 255) / 256, 256>>>(xn, dww, dwb, conv);
    gemm_mma_kernel<2,0><<<dim3(Dsz/CN, NROWS/128, 1), 256>>>(
        conv, Dsz, pww, Dsz, pwb, x, x1, Dsz, Dsz,
        nullptr, nullptr, nullptr, nullptr, nullptr, nullptr, nullptr);

    // ---- attention block ----
    layernorm_kernel<<<NROWS, 256>>>(x1, ln2g, ln2b, xn);
    // merged q/k/v projections (z selects weight/bias/output)
    gemm_mma_kernel<1,4><<<dim3(Dsz/CN, NROWS/128, 3), 256>>>(
        xn, Dsz, qw, Dsz, qb, nullptr, q, Dsz, Dsz,
        nullptr, kw, vw, kb, vb, k, v);
    transpose_v_kernel<<<dim3(Ssz/32, Dsz/32, Bsz), dim3(32, 8)>>>(v, vt);

    gemm_tn_small_kernel<<<dim3(Dsz/64, 1), 256>>>(relemb, Dsz, kw, Dsz, kb, posk, Dsz, Dsz);
    gemm_tn_small_kernel<<<dim3(Dsz/64, 1), 256>>>(relemb, Dsz, qw, Dsz, qb, posq, Dsz, Dsz);

    // merged c2p/p2c
    gemm_mma_kernel<0,3><<<dim3(1, Ssz/128, 2*Bsz*Hsz), 256>>>(
        q, Dsz, posk, Dsz, nullptr, nullptr, c2p, NPOS, DHsz,
        k, posq, nullptr, nullptr, nullptr, p2c, nullptr);

    // fused scores + bias + softmax + ctx
    flash_attn_kernel<<<dim3(Ssz/128, 1, Bsz*Hsz), 256, FA_SMEM>>>(
        q, k, vt, c2p, p2c, lut, ctx);

    gemm_mma_kernel<2,0><<<dim3(Dsz/CN, NROWS/128, 1), 256>>>(
        ctx, Dsz, ow, Dsz, ob, x1, x2, Dsz, Dsz,
        nullptr, nullptr, nullptr, nullptr, nullptr, nullptr, nullptr);

    // ---- FFN block ----
    layernorm_kernel<<<NROWS, 256>>>(x2, ln3g, ln3b, xn);
    gemm_mma_kernel<3,0><<<dim3(FFsz/CN, NROWS/128, 1), 256>>>(
        xn, Dsz, w1, Dsz, b1, nullptr, ff, FFsz, Dsz,
        nullptr, nullptr, nullptr, nullptr, nullptr, nullptr, nullptr);
    gemm_mma_kernel<2,0><<<dim3(Dsz/CN, NROWS/128, 1), 256>>>(
        ff, FFsz, w2, FFsz, b2, x2, out, Dsz, FFsz,
        nullptr, nullptr, nullptr, nullptr, nullptr, nullptr, nullptr);
}

// round 6
// speedup vs baseline: 1.0590x; 1.0590x over previous
#include <cuda_runtime.h>
#include <math.h>
#include <stdint.h>

#define Bsz 8
#define Ssz 1024
#define Dsz 512
#define Hsz 8
#define DHsz 64
#define FFsz 1024
#define NPOS 64          // 2*SPAN
#define NROWS (Bsz*Ssz)  // 8192

// ---------------- scratch (device globals; no allocation allowed) ------------
__device__ float g_xn  [Bsz*Ssz*Dsz];
__device__ float g_conv[Bsz*Ssz*Dsz];
__device__ float g_x1  [Bsz*Ssz*Dsz];
__device__ float g_x2  [Bsz*Ssz*Dsz];
__device__ float g_q   [Bsz*Ssz*Dsz];
__device__ float g_k   [Bsz*Ssz*Dsz];
__device__ float g_v   [Bsz*Ssz*Dsz];
__device__ float g_vt  [Bsz*Ssz*Dsz];   // [B, D, S]
__device__ float g_ctx [Bsz*Ssz*Dsz];
__device__ float g_posk[NPOS*Dsz];
__device__ float g_posq[NPOS*Dsz];
__device__ float g_c2p [Bsz*Hsz*Ssz*NPOS];
__device__ float g_p2c [Bsz*Hsz*Ssz*NPOS];
__device__ float g_ff  [Bsz*Ssz*FFsz];
__device__ int   g_lut [2*Ssz];

// ---------------- relative-position bucket LUT --------------------------------
__global__ void build_lut_kernel(int* __restrict__ lut) {
    int t = blockIdx.x * blockDim.x + threadIdx.x;
    if (t >= 2*Ssz - 1) return;
    int rel = t - (Ssz - 1);   // i - j
    const int mid = 16;        // BUCKETS/2
    int bucket;
    if (rel > -mid && rel < mid) {
        bucket = rel;
    } else {
        float absp = fabsf((float)rel);
        if (absp <= (float)mid) {
            bucket = rel;
        } else {
            float logp = ceilf(logf(absp / 16.0f) / logf(127.0f / 16.0f) * 15.0f) + 16.0f;
            bucket = (rel > 0 ? 1 : -1) * (int)logp;
        }
    }
    int idx = bucket + 32;
    idx = min(max(idx, 0), 63);
    lut[t] = idx;
}

// ---------------- LayerNorm (D=512, one block per row) ------------------------
__global__ void layernorm_kernel(const float* __restrict__ x,
                                 const float* __restrict__ g,
                                 const float* __restrict__ bb,
                                 float* __restrict__ out) {
    const float* xr = x + (size_t)blockIdx.x * Dsz;
    float* orow = out + (size_t)blockIdx.x * Dsz;
    int tid = threadIdx.x;  // 256
    float v0 = xr[tid], v1 = xr[tid + 256];
    float s = v0 + v1, ss = v0 * v0 + v1 * v1;
    __shared__ float r1[8], r2[8];
    #pragma unroll
    for (int o = 16; o; o >>= 1) {
        s  += __shfl_xor_sync(0xffffffffu, s, o);
        ss += __shfl_xor_sync(0xffffffffu, ss, o);
    }
    if ((tid & 31) == 0) { r1[tid >> 5] = s; r2[tid >> 5] = ss; }
    __syncthreads();
    float S1 = 0.f, S2 = 0.f;
    #pragma unroll
    for (int i = 0; i < 8; i++) { S1 += r1[i]; S2 += r2[i]; }
    float mean = S1 * (1.0f / Dsz);
    float var  = S2 * (1.0f / Dsz) - mean * mean;
    float rs = rsqrtf(var + 1e-5f);
    orow[tid]       = (v0 - mean) * rs * g[tid]       + bb[tid];
    orow[tid + 256] = (v1 - mean) * rs * g[tid + 256] + bb[tid + 256];
}

// ---------------- depthwise conv (K=3 along S) + bias + SiLU ------------------
__global__ void dwconv_silu_kernel(const float* __restrict__ xn,
                                   const float* __restrict__ w,
                                   const float* __restrict__ bias,
                                   float* __restrict__ out) {
    size_t idx = (size_t)blockIdx.x * blockDim.x + threadIdx.x;
    if (idx >= (size_t)Bsz * Ssz * Dsz) return;
    int d = (int)(idx % Dsz);
    int s = (int)((idx / Dsz) % Ssz);
    const float* base = xn + idx;
    float w0 = w[d * 3 + 0], w1 = w[d * 3 + 1], w2 = w[d * 3 + 2];
    float acc = bias[d] + base[0] * w1;
    if (s > 0)        acc += base[-Dsz] * w0;
    if (s < Ssz - 1)  acc += base[ Dsz] * w2;
    out[idx] = acc / (1.0f + expf(-acc));  // silu
}

// ---------------- V transpose: [B,S,D] -> [B,D,S] ------------------------------
__global__ void transpose_v_kernel(const float* __restrict__ v, float* __restrict__ vt) {
    __shared__ float tile[32][33];
    int b = blockIdx.z;
    int s0 = blockIdx.x * 32, d0 = blockIdx.y * 32;
    int tx = threadIdx.x, ty = threadIdx.y;  // 32 x 8
    #pragma unroll
    for (int j = 0; j < 32; j += 8)
        tile[ty + j][tx] = v[((size_t)b * Ssz + s0 + ty + j) * Dsz + d0 + tx];
    __syncthreads();
    #pragma unroll
    for (int j = 0; j < 32; j += 8)
        vt[((size_t)b * Dsz + d0 + ty + j) * Ssz + s0 + tx] = tile[tx][ty + j];
}

// ---------------- mma.tf32 + ldmatrix helpers ----------------------------------
__device__ __forceinline__ void mma_tf32(float c[4], const uint32_t a[4], const uint32_t b[2]) {
    asm volatile(
        "mma.sync.aligned.m16n8k8.row.col.f32.tf32.tf32.f32 "
        "{%0,%1,%2,%3}, {%4,%5,%6,%7}, {%8,%9}, {%0,%1,%2,%3};"
        : "+f"(c[0]), "+f"(c[1]), "+f"(c[2]), "+f"(c[3])
        : "r"(a[0]), "r"(a[1]), "r"(a[2]), "r"(a[3]), "r"(b[0]), "r"(b[1]));
}

__device__ __forceinline__ void ldsm_x4(uint32_t r[4], uint32_t addr) {
    asm volatile("ldmatrix.sync.aligned.m8n8.x4.shared.b16 {%0,%1,%2,%3}, [%4];"
                 : "=r"(r[0]), "=r"(r[1]), "=r"(r[2]), "=r"(r[3]) : "r"(addr));
}

#define CP_ASYNC16(dst_u32, src_ptr) \
    asm volatile("cp.async.ca.shared.global [%0], [%1], 16;" :: "r"(dst_u32), "l"(src_ptr))
#define CP_COMMIT() asm volatile("cp.async.commit_group;")
#define CP_WAIT2()  asm volatile("cp.async.wait_group 2;")
#define CP_WAIT1()  asm volatile("cp.async.wait_group 1;")
#define CP_WAIT0()  asm volatile("cp.async.wait_group 0;")

// ---------------- tensor-core TN GEMM (128xCN tiles, 4-stage, 1 barrier/iter) --
// C[m,n] = sum_k A[m,k] * W[n,k]
// EPI: 0 none, 1 +bias, 2 +bias+res, 3 silu(+bias)
// MODE: 0 plain, 3 pos-merged (z<64: q.posk -> c2p ; z>=64: k.posq -> p2c),
//       4 qkv-merged (z selects {qw,kw,vw})
#define SSTRIDE 20
#define NSTAGE 4

template<int CN, int EPI, int MODE>
__global__ void __launch_bounds__(256, 2) gemm_mma_kernel(
    const float* __restrict__ A0, int lda,
    const float* __restrict__ W0, int ldw,
    const float* __restrict__ bias0, const float* __restrict__ res,
    float* __restrict__ C0, int ldc, int K,
    const float* __restrict__ Aa, const float* __restrict__ Wa,
    const float* __restrict__ Wb2, const float* __restrict__ ba,
    const float* __restrict__ bb2, float* __restrict__ Ca, float* __restrict__ Cb)
{
    constexpr int NWN = CN / 32;     // warps along N
    constexpr int NWM = 8 / NWN;     // warps along M
    constexpr int MT  = 8 / NWM;     // m16 tiles per warp

    extern __shared__ float smem[];
    float* As = smem;                              // NSTAGE * 128 * SSTRIDE
    float* Ws = smem + NSTAGE * 128 * SSTRIDE;     // NSTAGE * CN  * SSTRIDE

    const int tid  = threadIdx.x;
    const int wid  = tid >> 5, lane = tid & 31;
    const int g    = lane >> 2, tg = lane & 3;
    const int wm   = wid % NWM, wn = wid / NWM;

    const int z = blockIdx.z;
    const float* A = A0; const float* W = W0; float* C = C0;
    const float* bias = bias0;
    if (MODE == 3) {
        int zz = z & 63, sel = z >> 6;
        int bb = zz >> 3, hh = zz & 7;
        A = (sel ? Aa : A0) + (size_t)bb * Ssz * Dsz + hh * DHsz;
        W = (sel ? Wa : W0) + hh * DHsz;
        C = (sel ? Ca : C0) + (size_t)zz * Ssz * NPOS;
    } else if (MODE == 4) {
        W    = (z == 0) ? W0 : (z == 1 ? Wa : Wb2);
        bias = (z == 0) ? bias0 : (z == 1 ? ba : bb2);
        C    = (z == 0) ? C0 : (z == 1 ? Ca : Cb);
    }

    const int m_cta = blockIdx.y * 128, n_cta = blockIdx.x * CN;

    const uint32_t sA = (uint32_t)__cvta_generic_to_shared(As);
    const uint32_t sW = (uint32_t)__cvta_generic_to_shared(Ws);

    const int qd = (tid & 3) * 4;
    const int rr = tid >> 2;

    auto fetch = [&](int t, int buf) {
        int k0 = t * 16;
        #pragma unroll
        for (int r = 0; r < 2; r++) {
            int row = rr + 64 * r;
            uint32_t d = sA + (uint32_t)(buf * 128 * SSTRIDE + row * SSTRIDE + qd) * 4u;
            CP_ASYNC16(d, A + (size_t)(m_cta + row) * lda + k0 + qd);
        }
        #pragma unroll
        for (int r = 0; r < CN / 64; r++) {
            int row = rr + 64 * r;
            uint32_t d = sW + (uint32_t)(buf * CN * SSTRIDE + row * SSTRIDE + qd) * 4u;
            CP_ASYNC16(d, W + (size_t)(n_cta + row) * ldw + k0 + qd);
        }
        CP_COMMIT();
    };

    // ldmatrix per-thread offsets (float units)
    const int lq = lane >> 3, lr = lane & 7;
    const int aoff = ((lq & 1) * 8 + lr) * SSTRIDE + (lq >> 1) * 4;  // A frag
    const int boff = ((lq >> 1) * 8 + lr) * SSTRIDE + (lq & 1) * 4;  // B frag pair

    float acc[MT][4][4] = {};

    const int T = K / 16;
    fetch(0, 0);
    fetch(1, 1);
    if (T > 2) fetch(2, 2);
    for (int it = 0; it < T; it++) {
        const int buf = it & (NSTAGE - 1);
        // exact wait: in-flight groups = min(3, T - it); need stage `it` done
        if (it < T - 2)      { CP_WAIT2(); }
        else if (it == T - 2){ CP_WAIT1(); }
        else                 { CP_WAIT0(); }
        __syncthreads();     // all warps done with buffer (it+1) % NSTAGE's prior use
        if (it + 3 < T) fetch(it + 3, (it + 3) & (NSTAGE - 1));

        const uint32_t bA = sA + (uint32_t)(buf * 128 * SSTRIDE) * 4u;
        const uint32_t bW = sW + (uint32_t)(buf * CN  * SSTRIDE) * 4u;
        #pragma unroll
        for (int ks = 0; ks < 2; ks++) {
            const int kk = ks * 8;
            uint32_t af[MT][4];
            #pragma unroll
            for (int im = 0; im < MT; im++)
                ldsm_x4(af[im], bA + (uint32_t)((wm * MT * 16 + im * 16) * SSTRIDE + aoff + kk) * 4u);
            uint32_t bf[2][4];   // each covers 2 n8-tiles
            #pragma unroll
            for (int ip = 0; ip < 2; ip++)
                ldsm_x4(bf[ip], bW + (uint32_t)((wn * 32 + ip * 16) * SSTRIDE + boff + kk) * 4u);
            #pragma unroll
            for (int im = 0; im < MT; im++)
                #pragma unroll
                for (int in = 0; in < 4; in++)
                    mma_tf32(acc[im][in], af[im], &bf[in >> 1][(in & 1) * 2]);
        }
    }

    #pragma unroll
    for (int im = 0; im < MT; im++) {
        int mrow0 = m_cta + wm * MT * 16 + im * 16 + g;
        #pragma unroll
        for (int in = 0; in < 4; in++) {
            int ncol0 = n_cta + wn * 32 + in * 8 + tg * 2;
            #pragma unroll
            for (int e = 0; e < 4; e++) {
                int m = mrow0 + ((e >= 2) ? 8 : 0);
                int n = ncol0 + (e & 1);
                float vv = acc[im][in][e];
                if (EPI == 1 || EPI == 2 || EPI == 3) vv += bias[n];
                if (EPI == 2) vv += res[(size_t)m * ldc + n];
                if (EPI == 3) vv = vv / (1.0f + expf(-vv));
                C[(size_t)m * ldc + n] = vv;
            }
        }
    }
}

#define GEMM_SMEM(CNv) (NSTAGE * (128 + (CNv)) * SSTRIDE * 4)

// ---------------- small SIMT GEMM (pos projections, M=64) ---------------------
#define TK 16
#define TPAD 68
__global__ void gemm_tn_small_kernel(const float* __restrict__ A, int lda,
                                     const float* __restrict__ W, int ldw,
                                     const float* __restrict__ bias,
                                     float* __restrict__ C, int ldc, int Kd) {
    int m0 = blockIdx.y * 64, n0 = blockIdx.x * 64;
    __shared__ float As[TK][TPAD];
    __shared__ float Ws2[TK][TPAD];
    const int tid = threadIdx.x;
    const int tx = tid & 15, ty = tid >> 4;
    const int lk = tid & 15, lm = tid >> 4;
    float acc[4][4] = {};
    for (int k0 = 0; k0 < Kd; k0 += TK) {
        #pragma unroll
        for (int r = 0; r < 4; r++) {
            As[lk][lm + 16 * r]  = A[(size_t)(m0 + lm + 16 * r) * lda + k0 + lk];
            Ws2[lk][lm + 16 * r] = W[(size_t)(n0 + lm + 16 * r) * ldw + k0 + lk];
        }
        __syncthreads();
        #pragma unroll
        for (int kk = 0; kk < TK; kk++) {
            float4 a = *(const float4*)&As[kk][ty * 4];
            float4 b = *(const float4*)&Ws2[kk][tx * 4];
            float av[4] = {a.x, a.y, a.z, a.w};
            float bv[4] = {b.x, b.y, b.z, b.w};
            #pragma unroll
            for (int i = 0; i < 4; i++)
                #pragma unroll
                for (int j = 0; j < 4; j++)
                    acc[i][j] += av[i] * bv[j];
        }
        __syncthreads();
    }
    #pragma unroll
    for (int i = 0; i < 4; i++) {
        int m = m0 + ty * 4 + i;
        #pragma unroll
        for (int j = 0; j < 4; j++) {
            int n = n0 + tx * 4 + j;
            C[(size_t)m * ldc + n] = acc[i][j] + bias[n];
        }
    }
}

// =========================== fused flash attention =============================
// One CTA per (z = b*H+h, i-tile of 128). 8 warps; warp w owns rows [w*16, w*16+16).
#define KST 68
#define PST 132
#define FA_SMEM ((128*KST + 64*PST + 128*PST) * 4)

__global__ void __launch_bounds__(256, 1) flash_attn_kernel(
    const float* __restrict__ qg, const float* __restrict__ kg,
    const float* __restrict__ vt,
    const float* __restrict__ c2p, const float* __restrict__ p2c,
    const int* __restrict__ lut, float* __restrict__ ctx)
{
    extern __shared__ float sm[];
    float* Kb = sm;                        // 128 x 68
    float* Vb = sm + 128*KST;              // 64 x 132
    float* Pb = sm + 128*KST + 64*PST;     // 128 x 132 (and Q stage @ stride 68)

    const int tid = threadIdx.x, w = tid >> 5, lane = tid & 31;
    const int g = lane >> 2, tg = lane & 3;
    const int z = blockIdx.z, bb = z >> 3, hh = z & 7;
    const int i0 = blockIdx.x * 128;

    const float* c2pz = c2p + (size_t)z * Ssz * NPOS;
    const float* p2cz = p2c + (size_t)z * Ssz * NPOS;

    const uint32_t sK = (uint32_t)__cvta_generic_to_shared(Kb);
    const uint32_t sV = (uint32_t)__cvta_generic_to_shared(Vb);
    const uint32_t sP = (uint32_t)__cvta_generic_to_shared(Pb);

    auto loadK = [&](int jt) {
        int j0 = jt * 128;
        #pragma unroll
        for (int c = 0; c < 8; c++) {
            int id = tid * 8 + c;
            int row = id >> 4, fcol = (id & 15) * 4;
            CP_ASYNC16(sK + (uint32_t)(row * KST + fcol) * 4u,
                       kg + ((size_t)bb * Ssz + j0 + row) * Dsz + hh * DHsz + fcol);
        }
        CP_COMMIT();
    };
    auto loadV = [&](int jt) {
        int j0 = jt * 128;
        #pragma unroll
        for (int c = 0; c < 8; c++) {
            int id = tid * 8 + c;
            int row = id >> 5, fcol = (id & 31) * 4;
            CP_ASYNC16(sV + (uint32_t)(row * PST + fcol) * 4u,
                       vt + ((size_t)bb * Dsz + hh * DHsz + row) * Ssz + j0 + fcol);
        }
        CP_COMMIT();
    };

    #pragma unroll
    for (int c = 0; c < 8; c++) {
        int id = tid * 8 + c;
        int row = id >> 4, fcol = (id & 15) * 4;
        CP_ASYNC16(sP + (uint32_t)(row * KST + fcol) * 4u,
                   qg + ((size_t)bb * Ssz + i0 + row) * Dsz + hh * DHsz + fcol);
    }
    CP_COMMIT();
    loadK(0);
    loadV(0);

    CP_WAIT2();          // Q done
    __syncthreads();

    const int lq = lane >> 3, lr = lane & 7;
    const int aoffQ = ((lq & 1) * 8 + lr) * KST + (lq >> 1) * 4;
    const int boffK = ((lq >> 1) * 8 + lr) * KST + (lq & 1) * 4;
    const int aoffP = ((lq & 1) * 8 + lr) * PST + (lq >> 1) * 4;
    const int boffV = ((lq >> 1) * 8 + lr) * PST + (lq & 1) * 4;

    uint32_t qf[8][4];
    #pragma unroll
    for (int kc = 0; kc < 8; kc++)
        ldsm_x4(qf[kc], sP + (uint32_t)((w * 16) * KST + aoffQ + kc * 8) * 4u);

    float acc_o[8][4] = {};
    float m_r[2] = {-1e30f, -1e30f};
    float l_r[2] = {0.f, 0.f};
    const float SCALE = 0.07216878364870323f;  // 1/sqrt(64*3)
    const int mg0 = i0 + w * 16 + g;

    for (int jt = 0; jt < 8; jt++) {
        const int j0 = jt * 128;
        CP_WAIT1();          // K_jt arrived
        __syncthreads();

        // ---- S = Q K^T ----
        float acc_s[16][4] = {};
        #pragma unroll
        for (int kc = 0; kc < 8; kc++) {
            #pragma unroll
            for (int ip = 0; ip < 8; ip++) {
                uint32_t bf[4];
                ldsm_x4(bf, sK + (uint32_t)((ip * 16) * KST + boffK + kc * 8) * 4u);
                mma_tf32(acc_s[ip * 2],     qf[kc], &bf[0]);
                mma_tf32(acc_s[ip * 2 + 1], qf[kc], &bf[2]);
            }
        }

        // ---- bias + online softmax ----
        float mx0 = -1e30f, mx1 = -1e30f;
        #pragma unroll
        for (int in = 0; in < 16; in++) {
            int nbase = j0 + in * 8 + tg * 2;
            #pragma unroll
            for (int e = 0; e < 4; e++) {
                int m = mg0 + ((e >= 2) ? 8 : 0);
                int n = nbase + (e & 1);
                int idx = __ldg(&lut[m - n + (Ssz - 1)]);
                float vv = (acc_s[in][e] + __ldg(&c2pz[(size_t)m * NPOS + idx])
                                         + __ldg(&p2cz[(size_t)n * NPOS + idx])) * SCALE;
                acc_s[in][e] = vv;
                if (e < 2) mx0 = fmaxf(mx0, vv); else mx1 = fmaxf(mx1, vv);
            }
        }
        mx0 = fmaxf(mx0, __shfl_xor_sync(0xffffffffu, mx0, 1));
        mx0 = fmaxf(mx0, __shfl_xor_sync(0xffffffffu, mx0, 2));
        mx1 = fmaxf(mx1, __shfl_xor_sync(0xffffffffu, mx1, 1));
        mx1 = fmaxf(mx1, __shfl_xor_sync(0xffffffffu, mx1, 2));
        float mn0 = fmaxf(m_r[0], mx0), mn1 = fmaxf(m_r[1], mx1);
        float al0 = __expf(m_r[0] - mn0), al1 = __expf(m_r[1] - mn1);
        float s0 = 0.f, s1 = 0.f;
        #pragma unroll
        for (int in = 0; in < 16; in++) {
            float p0 = __expf(acc_s[in][0] - mn0);
            float p1 = __expf(acc_s[in][1] - mn0);
            float p2 = __expf(acc_s[in][2] - mn1);
            float p3 = __expf(acc_s[in][3] - mn1);
            acc_s[in][0] = p0; acc_s[in][1] = p1; acc_s[in][2] = p2; acc_s[in][3] = p3;
            s0 += p0 + p1; s1 += p2 + p3;
        }
        l_r[0] = l_r[0] * al0 + s0;
        l_r[1] = l_r[1] * al1 + s1;
        m_r[0] = mn0; m_r[1] = mn1;
        #pragma unroll
        for (int nf = 0; nf < 8; nf++) {
            acc_o[nf][0] *= al0; acc_o[nf][1] *= al0;
            acc_o[nf][2] *= al1; acc_o[nf][3] *= al1;
        }

        __syncthreads();
        if (jt < 7) loadK(jt + 1);

        // ---- store P ----
        #pragma unroll
        for (int in = 0; in < 16; in++) {
            int col = in * 8 + tg * 2;
            *(float2*)&Pb[(w * 16 + g)     * PST + col] = make_float2(acc_s[in][0], acc_s[in][1]);
            *(float2*)&Pb[(w * 16 + g + 8) * PST + col] = make_float2(acc_s[in][2], acc_s[in][3]);
        }
        if (jt < 7) { CP_WAIT1(); } else { CP_WAIT0(); }  // V_jt arrived
        __syncthreads();

        // ---- O += P V ----
        #pragma unroll
        for (int kc2 = 0; kc2 < 16; kc2++) {
            uint32_t af[4];
            ldsm_x4(af, sP + (uint32_t)((w * 16) * PST + aoffP + kc2 * 8) * 4u);
            #pragma unroll
            for (int ip = 0; ip < 4; ip++) {
                uint32_t bf[4];
                ldsm_x4(bf, sV + (uint32_t)((ip * 16) * PST + boffV + kc2 * 8) * 4u);
                mma_tf32(acc_o[ip * 2],     af, &bf[0]);
                mma_tf32(acc_o[ip * 2 + 1], af, &bf[2]);
            }
        }
        __syncthreads();
        if (jt < 7) loadV(jt + 1);
    }

    // ---- finalize ----
    float l0 = l_r[0];
    l0 += __shfl_xor_sync(0xffffffffu, l0, 1);
    l0 += __shfl_xor_sync(0xffffffffu, l0, 2);
    float l1 = l_r[1];
    l1 += __shfl_xor_sync(0xffffffffu, l1, 1);
    l1 += __shfl_xor_sync(0xffffffffu, l1, 2);
    float inv0 = 1.0f / l0, inv1 = 1.0f / l1;
    float* c0 = ctx + ((size_t)bb * Ssz + mg0)     * Dsz + hh * DHsz;
    float* c1 = ctx + ((size_t)bb * Ssz + mg0 + 8) * Dsz + hh * DHsz;
    #pragma unroll
    for (int nf = 0; nf < 8; nf++) {
        int col = nf * 8 + tg * 2;
        *(float2*)&c0[col] = make_float2(acc_o[nf][0] * inv0, acc_o[nf][1] * inv0);
        *(float2*)&c1[col] = make_float2(acc_o[nf][2] * inv1, acc_o[nf][3] * inv1);
    }
}

// =============================== launch ========================================
extern "C" void kernel_launch(void* const* d_in, const int* in_sizes, int n_in,
                              void* d_out, int out_size) {
    const float* x      = (const float*)d_in[0];
    const float* ln1g   = (const float*)d_in[1];
    const float* ln1b   = (const float*)d_in[2];
    const float* dww    = (const float*)d_in[3];
    const float* dwb    = (const float*)d_in[4];
    const float* pww    = (const float*)d_in[5];
    const float* pwb    = (const float*)d_in[6];
    const float* ln2g   = (const float*)d_in[7];
    const float* ln2b   = (const float*)d_in[8];
    const float* qw     = (const float*)d_in[9];
    const float* qb     = (const float*)d_in[10];
    const float* kw     = (const float*)d_in[11];
    const float* kb     = (const float*)d_in[12];
    const float* vw     = (const float*)d_in[13];
    const float* vb     = (const float*)d_in[14];
    const float* ow     = (const float*)d_in[15];
    const float* ob     = (const float*)d_in[16];
    const float* relemb = (const float*)d_in[17];
    const float* ln3g   = (const float*)d_in[18];
    const float* ln3b   = (const float*)d_in[19];
    const float* w1     = (const float*)d_in[20];
    const float* b1     = (const float*)d_in[21];
    const float* w2     = (const float*)d_in[22];
    const float* b2     = (const float*)d_in[23];
    float* out = (float*)d_out;

    float *xn, *conv, *x1, *x2, *q, *k, *v, *vt, *ctx, *posk, *posq, *c2p, *p2c, *ff;
    int* lut;
    cudaGetSymbolAddress((void**)&xn,   g_xn);
    cudaGetSymbolAddress((void**)&conv, g_conv);
    cudaGetSymbolAddress((void**)&x1,   g_x1);
    cudaGetSymbolAddress((void**)&x2,   g_x2);
    cudaGetSymbolAddress((void**)&q,    g_q);
    cudaGetSymbolAddress((void**)&k,    g_k);
    cudaGetSymbolAddress((void**)&v,    g_v);
    cudaGetSymbolAddress((void**)&vt,   g_vt);
    cudaGetSymbolAddress((void**)&ctx,  g_ctx);
    cudaGetSymbolAddress((void**)&posk, g_posk);
    cudaGetSymbolAddress((void**)&posq, g_posq);
    cudaGetSymbolAddress((void**)&c2p,  g_c2p);
    cudaGetSymbolAddress((void**)&p2c,  g_p2c);
    cudaGetSymbolAddress((void**)&ff,   g_ff);
    cudaGetSymbolAddress((void**)&lut,  g_lut);

    static int attr_set = 0;
    if (!attr_set) {
        cudaFuncSetAttribute(flash_attn_kernel,
                             cudaFuncAttributeMaxDynamicSharedMemorySize, FA_SMEM);
        cudaFuncSetAttribute(gemm_mma_kernel<128,2,0>,
                             cudaFuncAttributeMaxDynamicSharedMemorySize, GEMM_SMEM(128));
        cudaFuncSetAttribute(gemm_mma_kernel<128,1,4>,
                             cudaFuncAttributeMaxDynamicSharedMemorySize, GEMM_SMEM(128));
        cudaFuncSetAttribute(gemm_mma_kernel<128,3,0>,
                             cudaFuncAttributeMaxDynamicSharedMemorySize, GEMM_SMEM(128));
        cudaFuncSetAttribute(gemm_mma_kernel<64,0,3>,
                             cudaFuncAttributeMaxDynamicSharedMemorySize, GEMM_SMEM(64));
        attr_set = 1;
    }

    build_lut_kernel<<<8, 256>>>(lut);

    // ---- conv block ----
    layernorm_kernel<<<NROWS, 256>>>(x, ln1g, ln1b, xn);
    dwconv_silu_kernel<<<(Bsz*Ssz*Dsz + 255) / 256, 256>>>(xn, dww, dwb, conv);
    gemm_mma_kernel<128,2,0><<<dim3(Dsz/128, NROWS/128, 1), 256, GEMM_SMEM(128)>>>(
        conv, Dsz, pww, Dsz, pwb, x, x1, Dsz, Dsz,
        nullptr, nullptr, nullptr, nullptr, nullptr, nullptr, nullptr);

    // ---- attention block ----
    layernorm_kernel<<<NROWS, 256>>>(x1, ln2g, ln2b, xn);
    // merged q/k/v projections (z selects weight/bias/output)
    gemm_mma_kernel<128,1,4><<<dim3(Dsz/128, NROWS/128, 3), 256, GEMM_SMEM(128)>>>(
        xn, Dsz, qw, Dsz, qb, nullptr, q, Dsz, Dsz,
        nullptr, kw, vw, kb, vb, k, v);
    transpose_v_kernel<<<dim3(Ssz/32, Dsz/32, Bsz), dim3(32, 8)>>>(v, vt);

    gemm_tn_small_kernel<<<dim3(Dsz/64, 1), 256>>>(relemb, Dsz, kw, Dsz, kb, posk, Dsz, Dsz);
    gemm_tn_small_kernel<<<dim3(Dsz/64, 1), 256>>>(relemb, Dsz, qw, Dsz, qb, posq, Dsz, Dsz);

    // merged c2p/p2c
    gemm_mma_kernel<64,0,3><<<dim3(1, Ssz/128, 2*Bsz*Hsz), 256, GEMM_SMEM(64)>>>(
        q, Dsz, posk, Dsz, nullptr, nullptr, c2p, NPOS, DHsz,
        k, posq, nullptr, nullptr, nullptr, p2c, nullptr);

    // fused scores + bias + softmax + ctx
    flash_attn_kernel<<<dim3(Ssz/128, 1, Bsz*Hsz), 256, FA_SMEM>>>(
        q, k, vt, c2p, p2c, lut, ctx);

    gemm_mma_kernel<128,2,0><<<dim3(Dsz/128, NROWS/128, 1), 256, GEMM_SMEM(128)>>>(
        ctx, Dsz, ow, Dsz, ob, x1, x2, Dsz, Dsz,
        nullptr, nullptr, nullptr, nullptr, nullptr, nullptr, nullptr);

    // ---- FFN block ----
    layernorm_kernel<<<NROWS, 256>>>(x2, ln3g, ln3b, xn);
    gemm_mma_kernel<128,3,0><<<dim3(FFsz/128, NROWS/128, 1), 256, GEMM_SMEM(128)>>>(
        xn, Dsz, w1, Dsz, b1, nullptr, ff, FFsz, Dsz,
        nullptr, nullptr, nullptr, nullptr, nullptr, nullptr, nullptr);
    gemm_mma_kernel<128,2,0><<<dim3(Dsz/128, NROWS/128, 1), 256, GEMM_SMEM(128)>>>(
        ff, FFsz, w2, FFsz, b2, x2, out, Dsz, FFsz,
        nullptr, nullptr, nullptr, nullptr, nullptr, nullptr, nullptr);
}

// round 8
// speedup vs baseline: 1.1101x; 1.0483x over previous
#include <cuda_runtime.h>
#include <math.h>
#include <stdint.h>

#define Bsz 8
#define Ssz 1024
#define Dsz 512
#define Hsz 8
#define DHsz 64
#define FFsz 1024
#define NPOS 64          // 2*SPAN
#define NROWS (Bsz*Ssz)  // 8192

// ---------------- scratch (device globals; no allocation allowed) ------------
__device__ float g_xn  [Bsz*Ssz*Dsz];
__device__ float g_conv[Bsz*Ssz*Dsz];
__device__ float g_x1  [Bsz*Ssz*Dsz];
__device__ float g_x2  [Bsz*Ssz*Dsz];
__device__ float g_q   [Bsz*Ssz*Dsz];
__device__ float g_k   [Bsz*Ssz*Dsz];
__device__ float g_v   [Bsz*Ssz*Dsz];
__device__ float g_vt  [Bsz*Ssz*Dsz];   // [B, D, S]
__device__ float g_ctx [Bsz*Ssz*Dsz];
__device__ float g_posk[NPOS*Dsz];
__device__ float g_posq[NPOS*Dsz];
__device__ float g_c2p [Bsz*Hsz*Ssz*NPOS];
__device__ float g_p2c [Bsz*Hsz*Ssz*NPOS];
__device__ float g_ff  [Bsz*Ssz*FFsz];
__device__ int   g_lut [2*Ssz];

// ---------------- relative-position bucket LUT --------------------------------
__global__ void build_lut_kernel(int* __restrict__ lut) {
    int t = blockIdx.x * blockDim.x + threadIdx.x;
    if (t >= 2*Ssz - 1) return;
    int rel = t - (Ssz - 1);   // i - j
    const int mid = 16;        // BUCKETS/2
    int bucket;
    if (rel > -mid && rel < mid) {
        bucket = rel;
    } else {
        float absp = fabsf((float)rel);
        if (absp <= (float)mid) {
            bucket = rel;
        } else {
            float logp = ceilf(logf(absp / 16.0f) / logf(127.0f / 16.0f) * 15.0f) + 16.0f;
            bucket = (rel > 0 ? 1 : -1) * (int)logp;
        }
    }
    int idx = bucket + 32;
    idx = min(max(idx, 0), 63);
    lut[t] = idx;
}

// ---------------- LayerNorm (D=512, one block per row) ------------------------
__global__ void layernorm_kernel(const float* __restrict__ x,
                                 const float* __restrict__ g,
                                 const float* __restrict__ bb,
                                 float* __restrict__ out) {
    const float* xr = x + (size_t)blockIdx.x * Dsz;
    float* orow = out + (size_t)blockIdx.x * Dsz;
    int tid = threadIdx.x;  // 256
    float v0 = xr[tid], v1 = xr[tid + 256];
    float s = v0 + v1, ss = v0 * v0 + v1 * v1;
    __shared__ float r1[8], r2[8];
    #pragma unroll
    for (int o = 16; o; o >>= 1) {
        s  += __shfl_xor_sync(0xffffffffu, s, o);
        ss += __shfl_xor_sync(0xffffffffu, ss, o);
    }
    if ((tid & 31) == 0) { r1[tid >> 5] = s; r2[tid >> 5] = ss; }
    __syncthreads();
    float S1 = 0.f, S2 = 0.f;
    #pragma unroll
    for (int i = 0; i < 8; i++) { S1 += r1[i]; S2 += r2[i]; }
    float mean = S1 * (1.0f / Dsz);
    float var  = S2 * (1.0f / Dsz) - mean * mean;
    float rs = rsqrtf(var + 1e-5f);
    orow[tid]       = (v0 - mean) * rs * g[tid]       + bb[tid];
    orow[tid + 256] = (v1 - mean) * rs * g[tid + 256] + bb[tid + 256];
}

// ---------------- depthwise conv (K=3 along S) + bias + SiLU ------------------
__global__ void dwconv_silu_kernel(const float* __restrict__ xn,
                                   const float* __restrict__ w,
                                   const float* __restrict__ bias,
                                   float* __restrict__ out) {
    size_t idx = (size_t)blockIdx.x * blockDim.x + threadIdx.x;
    if (idx >= (size_t)Bsz * Ssz * Dsz) return;
    int d = (int)(idx % Dsz);
    int s = (int)((idx / Dsz) % Ssz);
    const float* base = xn + idx;
    float w0 = w[d * 3 + 0], w1 = w[d * 3 + 1], w2 = w[d * 3 + 2];
    float acc = bias[d] + base[0] * w1;
    if (s > 0)        acc += base[-Dsz] * w0;
    if (s < Ssz - 1)  acc += base[ Dsz] * w2;
    out[idx] = acc / (1.0f + expf(-acc));  // silu
}

// ---------------- V transpose: [B,S,D] -> [B,D,S] ------------------------------
__global__ void transpose_v_kernel(const float* __restrict__ v, float* __restrict__ vt) {
    __shared__ float tile[32][33];
    int b = blockIdx.z;
    int s0 = blockIdx.x * 32, d0 = blockIdx.y * 32;
    int tx = threadIdx.x, ty = threadIdx.y;  // 32 x 8
    #pragma unroll
    for (int j = 0; j < 32; j += 8)
        tile[ty + j][tx] = v[((size_t)b * Ssz + s0 + ty + j) * Dsz + d0 + tx];
    __syncthreads();
    #pragma unroll
    for (int j = 0; j < 32; j += 8)
        vt[((size_t)b * Dsz + d0 + ty + j) * Ssz + s0 + tx] = tile[tx][ty + j];
}

// ---------------- mma.tf32 + ldmatrix helpers ----------------------------------
__device__ __forceinline__ void mma_tf32(float c[4], const uint32_t a[4], const uint32_t b[2]) {
    asm volatile(
        "mma.sync.aligned.m16n8k8.row.col.f32.tf32.tf32.f32 "
        "{%0,%1,%2,%3}, {%4,%5,%6,%7}, {%8,%9}, {%0,%1,%2,%3};"
        : "+f"(c[0]), "+f"(c[1]), "+f"(c[2]), "+f"(c[3])
        : "r"(a[0]), "r"(a[1]), "r"(a[2]), "r"(a[3]), "r"(b[0]), "r"(b[1]));
}

__device__ __forceinline__ void ldsm_x4(uint32_t r[4], uint32_t addr) {
    asm volatile("ldmatrix.sync.aligned.m8n8.x4.shared.b16 {%0,%1,%2,%3}, [%4];"
                 : "=r"(r[0]), "=r"(r[1]), "=r"(r[2]), "=r"(r[3]) : "r"(addr));
}

#define CP_ASYNC16(dst_u32, src_ptr) \
    asm volatile("cp.async.ca.shared.global [%0], [%1], 16;" :: "r"(dst_u32), "l"(src_ptr))
#define CP_COMMIT() asm volatile("cp.async.commit_group;")
#define CP_WAIT2()  asm volatile("cp.async.wait_group 2;")
#define CP_WAIT1()  asm volatile("cp.async.wait_group 1;")
#define CP_WAIT0()  asm volatile("cp.async.wait_group 0;")

// ---------------- tensor-core TN GEMM (128xCN tiles, 4-stage, 1 barrier/iter) --
// C[m,n] = sum_k A[m,k] * W[n,k]
// EPI: 0 none, 1 +bias, 2 +bias+res, 3 silu(+bias)
// MODE: 0 plain, 4 qkv-merged (z selects {qw,kw,vw})
#define SSTRIDE 20
#define NSTAGE 4
#define GEMM_SMEM(CNv) (NSTAGE * (128 + (CNv)) * SSTRIDE * 4)

template<int CN, int EPI, int MODE>
__global__ void __launch_bounds__(256, 2) gemm_mma_kernel(
    const float* __restrict__ A0, int lda,
    const float* __restrict__ W0, int ldw,
    const float* __restrict__ bias0, const float* __restrict__ res,
    float* __restrict__ C0, int ldc, int K,
    const float* __restrict__ Aa, const float* __restrict__ Wa,
    const float* __restrict__ Wb2, const float* __restrict__ ba,
    const float* __restrict__ bb2, float* __restrict__ Ca, float* __restrict__ Cb)
{
    constexpr int NWN = CN / 32;     // warps along N
    constexpr int NWM = 8 / NWN;     // warps along M
    constexpr int MT  = 8 / NWM;     // m16 tiles per warp

    extern __shared__ float smem[];
    float* As = smem;
    float* Ws = smem + NSTAGE * 128 * SSTRIDE;

    const int tid  = threadIdx.x;
    const int wid  = tid >> 5, lane = tid & 31;
    const int g    = lane >> 2, tg = lane & 3;
    const int wm   = wid % NWM, wn = wid / NWM;

    const int z = blockIdx.z;
    const float* A = A0; const float* W = W0; float* C = C0;
    const float* bias = bias0;
    if (MODE == 4) {
        W    = (z == 0) ? W0 : (z == 1 ? Wa : Wb2);
        bias = (z == 0) ? bias0 : (z == 1 ? ba : bb2);
        C    = (z == 0) ? C0 : (z == 1 ? Ca : Cb);
    }

    const int m_cta = blockIdx.y * 128, n_cta = blockIdx.x * CN;

    const uint32_t sA = (uint32_t)__cvta_generic_to_shared(As);
    const uint32_t sW = (uint32_t)__cvta_generic_to_shared(Ws);

    const int qd = (tid & 3) * 4;
    const int rr = tid >> 2;

    auto fetch = [&](int t, int buf) {
        int k0 = t * 16;
        #pragma unroll
        for (int r = 0; r < 2; r++) {
            int row = rr + 64 * r;
            uint32_t d = sA + (uint32_t)(buf * 128 * SSTRIDE + row * SSTRIDE + qd) * 4u;
            CP_ASYNC16(d, A + (size_t)(m_cta + row) * lda + k0 + qd);
        }
        #pragma unroll
        for (int r = 0; r < CN / 64; r++) {
            int row = rr + 64 * r;
            uint32_t d = sW + (uint32_t)(buf * CN * SSTRIDE + row * SSTRIDE + qd) * 4u;
            CP_ASYNC16(d, W + (size_t)(n_cta + row) * ldw + k0 + qd);
        }
        CP_COMMIT();
    };

    const int lq = lane >> 3, lr = lane & 7;
    const int aoff = ((lq & 1) * 8 + lr) * SSTRIDE + (lq >> 1) * 4;
    const int boff = ((lq >> 1) * 8 + lr) * SSTRIDE + (lq & 1) * 4;

    float acc[MT][4][4] = {};

    const int T = K / 16;
    fetch(0, 0);
    fetch(1, 1);
    if (T > 2) fetch(2, 2);
    for (int it = 0; it < T; it++) {
        const int buf = it & (NSTAGE - 1);
        if (it < T - 2)       { CP_WAIT2(); }
        else if (it == T - 2) { CP_WAIT1(); }
        else                  { CP_WAIT0(); }
        __syncthreads();
        if (it + 3 < T) fetch(it + 3, (it + 3) & (NSTAGE - 1));

        const uint32_t bA = sA + (uint32_t)(buf * 128 * SSTRIDE) * 4u;
        const uint32_t bW = sW + (uint32_t)(buf * CN  * SSTRIDE) * 4u;
        #pragma unroll
        for (int ks = 0; ks < 2; ks++) {
            const int kk = ks * 8;
            uint32_t af[MT][4];
            #pragma unroll
            for (int im = 0; im < MT; im++)
                ldsm_x4(af[im], bA + (uint32_t)((wm * MT * 16 + im * 16) * SSTRIDE + aoff + kk) * 4u);
            uint32_t bf[2][4];
            #pragma unroll
            for (int ip = 0; ip < 2; ip++)
                ldsm_x4(bf[ip], bW + (uint32_t)((wn * 32 + ip * 16) * SSTRIDE + boff + kk) * 4u);
            #pragma unroll
            for (int im = 0; im < MT; im++)
                #pragma unroll
                for (int in = 0; in < 4; in++)
                    mma_tf32(acc[im][in], af[im], &bf[in >> 1][(in & 1) * 2]);
        }
    }

    #pragma unroll
    for (int im = 0; im < MT; im++) {
        int mrow0 = m_cta + wm * MT * 16 + im * 16 + g;
        #pragma unroll
        for (int in = 0; in < 4; in++) {
            int ncol0 = n_cta + wn * 32 + in * 8 + tg * 2;
            #pragma unroll
            for (int e = 0; e < 4; e++) {
                int m = mrow0 + ((e >= 2) ? 8 : 0);
                int n = ncol0 + (e & 1);
                float vv = acc[im][in][e];
                if (EPI == 1 || EPI == 2 || EPI == 3) vv += bias[n];
                if (EPI == 2) vv += res[(size_t)m * ldc + n];
                if (EPI == 3) vv = vv / (1.0f + expf(-vv));
                C[(size_t)m * ldc + n] = vv;
            }
        }
    }
}

// ---------------- mma GEMM for pos projections (small N=64, K=64) --------------
template<int CN>
__global__ void __launch_bounds__(256, 2) gemm_pos_kernel(
    const float* __restrict__ A0,
    const float* __restrict__ W0,
    float* __restrict__ C0,
    const float* __restrict__ Aa, const float* __restrict__ Wa,
    float* __restrict__ Ca)
{
    constexpr int NWN = CN / 32;
    constexpr int NWM = 8 / NWN;
    constexpr int MT  = 8 / NWM;
    const int K = DHsz;

    extern __shared__ float smem[];
    float* As = smem;
    float* Ws = smem + NSTAGE * 128 * SSTRIDE;

    const int tid  = threadIdx.x;
    const int wid  = tid >> 5, lane = tid & 31;
    const int g    = lane >> 2, tg = lane & 3;
    const int wm   = wid % NWM, wn = wid / NWM;

    int zz = blockIdx.z & 63, sel = blockIdx.z >> 6;
    int bb = zz >> 3, hh = zz & 7;
    const float* A = (sel ? Aa : A0) + (size_t)bb * Ssz * Dsz + hh * DHsz;
    const float* W = (sel ? Wa : W0) + hh * DHsz;
    float* C = (sel ? Ca : C0) + (size_t)zz * Ssz * NPOS;

    const int m_cta = blockIdx.y * 128;

    const uint32_t sA = (uint32_t)__cvta_generic_to_shared(As);
    const uint32_t sW = (uint32_t)__cvta_generic_to_shared(Ws);
    const int qd = (tid & 3) * 4;
    const int rr = tid >> 2;

    auto fetch = [&](int t, int buf) {
        int k0 = t * 16;
        #pragma unroll
        for (int r = 0; r < 2; r++) {
            int row = rr + 64 * r;
            CP_ASYNC16(sA + (uint32_t)(buf * 128 * SSTRIDE + row * SSTRIDE + qd) * 4u,
                       A + (size_t)(m_cta + row) * Dsz + k0 + qd);
        }
        if (rr < CN)
            CP_ASYNC16(sW + (uint32_t)(buf * CN * SSTRIDE + rr * SSTRIDE + qd) * 4u,
                       W + (size_t)rr * Dsz + k0 + qd);
        CP_COMMIT();
    };

    const int lq = lane >> 3, lr = lane & 7;
    const int aoff = ((lq & 1) * 8 + lr) * SSTRIDE + (lq >> 1) * 4;
    const int boff = ((lq >> 1) * 8 + lr) * SSTRIDE + (lq & 1) * 4;

    float acc[MT][4][4] = {};
    const int T = K / 16;   // 4
    fetch(0, 0); fetch(1, 1); if (T > 2) fetch(2, 2);
    for (int it = 0; it < T; it++) {
        const int buf = it & (NSTAGE - 1);
        if (it < T - 2)       { CP_WAIT2(); }
        else if (it == T - 2) { CP_WAIT1(); }
        else                  { CP_WAIT0(); }
        __syncthreads();
        if (it + 3 < T) fetch(it + 3, (it + 3) & (NSTAGE - 1));
        const uint32_t bA = sA + (uint32_t)(buf * 128 * SSTRIDE) * 4u;
        const uint32_t bW = sW + (uint32_t)(buf * CN  * SSTRIDE) * 4u;
        #pragma unroll
        for (int ks = 0; ks < 2; ks++) {
            const int kk = ks * 8;
            uint32_t af[MT][4];
            #pragma unroll
            for (int im = 0; im < MT; im++)
                ldsm_x4(af[im], bA + (uint32_t)((wm * MT * 16 + im * 16) * SSTRIDE + aoff + kk) * 4u);
            uint32_t bf[2][4];
            #pragma unroll
            for (int ip = 0; ip < 2; ip++)
                ldsm_x4(bf[ip], bW + (uint32_t)((wn * 32 + ip * 16) * SSTRIDE + boff + kk) * 4u);
            #pragma unroll
            for (int im = 0; im < MT; im++)
                #pragma unroll
                for (int in = 0; in < 4; in++)
                    mma_tf32(acc[im][in], af[im], &bf[in >> 1][(in & 1) * 2]);
        }
    }

    #pragma unroll
    for (int im = 0; im < MT; im++) {
        int mrow0 = m_cta + wm * MT * 16 + im * 16 + g;
        #pragma unroll
        for (int in = 0; in < 4; in++) {
            int ncol0 = wn * 32 + in * 8 + tg * 2;
            #pragma unroll
            for (int e = 0; e < 4; e++) {
                int m = mrow0 + ((e >= 2) ? 8 : 0);
                int nn = ncol0 + (e & 1);
                C[(size_t)m * NPOS + nn] = acc[im][in][e];
            }
        }
    }
}

// ---------------- small SIMT GEMM (pos-emb projections, M=64) ------------------
#define TK 16
#define TPAD 68
__global__ void gemm_tn_small_kernel(const float* __restrict__ A, int lda,
                                     const float* __restrict__ W, int ldw,
                                     const float* __restrict__ bias,
                                     float* __restrict__ C, int ldc, int Kd) {
    int m0 = blockIdx.y * 64, n0 = blockIdx.x * 64;
    __shared__ float As[TK][TPAD];
    __shared__ float Ws2[TK][TPAD];
    const int tid = threadIdx.x;
    const int tx = tid & 15, ty = tid >> 4;
    const int lk = tid & 15, lm = tid >> 4;
    float acc[4][4] = {};
    for (int k0 = 0; k0 < Kd; k0 += TK) {
        #pragma unroll
        for (int r = 0; r < 4; r++) {
            As[lk][lm + 16 * r]  = A[(size_t)(m0 + lm + 16 * r) * lda + k0 + lk];
            Ws2[lk][lm + 16 * r] = W[(size_t)(n0 + lm + 16 * r) * ldw + k0 + lk];
        }
        __syncthreads();
        #pragma unroll
        for (int kk = 0; kk < TK; kk++) {
            float4 a = *(const float4*)&As[kk][ty * 4];
            float4 b = *(const float4*)&Ws2[kk][tx * 4];
            float av[4] = {a.x, a.y, a.z, a.w};
            float bv[4] = {b.x, b.y, b.z, b.w};
            #pragma unroll
            for (int i = 0; i < 4; i++)
                #pragma unroll
                for (int j = 0; j < 4; j++)
                    acc[i][j] += av[i] * bv[j];
        }
        __syncthreads();
    }
    #pragma unroll
    for (int i = 0; i < 4; i++) {
        int m = m0 + ty * 4 + i;
        #pragma unroll
        for (int j = 0; j < 4; j++) {
            int n = n0 + tx * 4 + j;
            C[(size_t)m * ldc + n] = acc[i][j] + bias[n];
        }
    }
}

// =========================== fused flash attention =============================
// One CTA per (z = b*H+h, i-tile of 128). 8 warps; warp w owns rows [w*16, w*16+16).
// j-tile = 64 (16 iters). smem small enough for 2 CTAs/SM. lut cached in smem.
#define FST 68
#define FA_KB_OFF   0
#define FA_VB_OFF   (64*FST)
#define FA_PB_OFF   (128*FST)
#define FA_LUT_OFF  (256*FST)
#define FA_SMEM     ((256*FST + 2048) * 4)

__global__ void __launch_bounds__(256, 2) flash_attn_kernel(
    const float* __restrict__ qg, const float* __restrict__ kg,
    const float* __restrict__ vt,
    const float* __restrict__ c2p, const float* __restrict__ p2c,
    const int* __restrict__ lut, float* __restrict__ ctx)
{
    extern __shared__ float sm[];
    float* Kb = sm + FA_KB_OFF;            // 64 x 68
    float* Vb = sm + FA_VB_OFF;            // 64 x 68  (rows = d, cols = j)
    float* Pb = sm + FA_PB_OFF;            // 128 x 68 (Q staging, then P)
    int*   lut_s = (int*)(sm + FA_LUT_OFF);

    const int tid = threadIdx.x, w = tid >> 5, lane = tid & 31;
    const int g = lane >> 2, tg = lane & 3;
    const int z = blockIdx.z, bb = z >> 3, hh = z & 7;
    const int i0 = blockIdx.x * 128;

    const float* c2pz = c2p + (size_t)z * Ssz * NPOS;
    const float* p2cz = p2c + (size_t)z * Ssz * NPOS;

    const uint32_t sK = (uint32_t)__cvta_generic_to_shared(Kb);
    const uint32_t sV = (uint32_t)__cvta_generic_to_shared(Vb);
    const uint32_t sP = (uint32_t)__cvta_generic_to_shared(Pb);

    // lut -> smem (visible after the prologue __syncthreads)
    #pragma unroll
    for (int t = 0; t < 8; t++) {
        int idx = tid + 256 * t;
        if (idx < 2 * Ssz - 1) lut_s[idx] = lut[idx];
    }

    auto loadK = [&](int jt) {   // K tile: 64 rows (j) x 64 d
        int j0 = jt * 64;
        #pragma unroll
        for (int c = 0; c < 4; c++) {
            int id = tid * 4 + c;
            int row = id >> 4, fcol = (id & 15) * 4;
            CP_ASYNC16(sK + (uint32_t)(row * FST + fcol) * 4u,
                       kg + ((size_t)bb * Ssz + j0 + row) * Dsz + hh * DHsz + fcol);
        }
        CP_COMMIT();
    };
    auto loadV = [&](int jt) {   // V tile: 64 rows (d) x 64 j
        int j0 = jt * 64;
        #pragma unroll
        for (int c = 0; c < 4; c++) {
            int id = tid * 4 + c;
            int row = id >> 4, fcol = (id & 15) * 4;
            CP_ASYNC16(sV + (uint32_t)(row * FST + fcol) * 4u,
                       vt + ((size_t)bb * Dsz + hh * DHsz + row) * Ssz + j0 + fcol);
        }
        CP_COMMIT();
    };

    // prologue: Q -> Pb (128 x 64, stride FST), then K0, V0
    #pragma unroll
    for (int c = 0; c < 8; c++) {
        int id = tid * 8 + c;
        int row = id >> 4, fcol = (id & 15) * 4;
        CP_ASYNC16(sP + (uint32_t)(row * FST + fcol) * 4u,
                   qg + ((size_t)bb * Ssz + i0 + row) * Dsz + hh * DHsz + fcol);
    }
    CP_COMMIT();
    loadK(0);
    loadV(0);

    CP_WAIT2();          // Q done
    __syncthreads();     // also publishes lut_s

    const int lq = lane >> 3, lr = lane & 7;
    const int aoffA = ((lq & 1) * 8 + lr) * FST + (lq >> 1) * 4;   // A frags (Q/P)
    const int boffB = ((lq >> 1) * 8 + lr) * FST + (lq & 1) * 4;   // B frags (K/V)

    uint32_t qf[8][4];
    #pragma unroll
    for (int kc = 0; kc < 8; kc++)
        ldsm_x4(qf[kc], sP + (uint32_t)((w * 16) * FST + aoffA + kc * 8) * 4u);

    float acc_o[8][4] = {};
    float m_r[2] = {-1e30f, -1e30f};
    float l_r[2] = {0.f, 0.f};
    const float SCALE = 0.07216878364870323f;  // 1/sqrt(64*3)
    const int mg0 = i0 + w * 16 + g;

    for (int jt = 0; jt < 16; jt++) {
        const int j0 = jt * 64;
        CP_WAIT1();          // K_jt arrived (V_jt pending)
        __syncthreads();

        // ---- S = Q K^T (64 cols) ----
        float acc_s[8][4] = {};
        #pragma unroll
        for (int kc = 0; kc < 8; kc++) {
            #pragma unroll
            for (int ip = 0; ip < 4; ip++) {
                uint32_t bf[4];
                ldsm_x4(bf, sK + (uint32_t)((ip * 16) * FST + boffB + kc * 8) * 4u);
                mma_tf32(acc_s[ip * 2],     qf[kc], &bf[0]);
                mma_tf32(acc_s[ip * 2 + 1], qf[kc], &bf[2]);
            }
        }

        // ---- bias + online softmax ----
        float mx0 = -1e30f, mx1 = -1e30f;
        #pragma unroll
        for (int in = 0; in < 8; in++) {
            int nbase = j0 + in * 8 + tg * 2;
            #pragma unroll
            for (int e = 0; e < 4; e++) {
                int m = mg0 + ((e >= 2) ? 8 : 0);
                int n = nbase + (e & 1);
                int idx = lut_s[m - n + (Ssz - 1)];
                float vv = (acc_s[in][e] + __ldg(&c2pz[(size_t)m * NPOS + idx])
                                         + __ldg(&p2cz[(size_t)n * NPOS + idx])) * SCALE;
                acc_s[in][e] = vv;
                if (e < 2) mx0 = fmaxf(mx0, vv); else mx1 = fmaxf(mx1, vv);
            }
        }
        mx0 = fmaxf(mx0, __shfl_xor_sync(0xffffffffu, mx0, 1));
        mx0 = fmaxf(mx0, __shfl_xor_sync(0xffffffffu, mx0, 2));
        mx1 = fmaxf(mx1, __shfl_xor_sync(0xffffffffu, mx1, 1));
        mx1 = fmaxf(mx1, __shfl_xor_sync(0xffffffffu, mx1, 2));
        float mn0 = fmaxf(m_r[0], mx0), mn1 = fmaxf(m_r[1], mx1);
        float al0 = __expf(m_r[0] - mn0), al1 = __expf(m_r[1] - mn1);
        float s0 = 0.f, s1 = 0.f;
        #pragma unroll
        for (int in = 0; in < 8; in++) {
            float p0 = __expf(acc_s[in][0] - mn0);
            float p1 = __expf(acc_s[in][1] - mn0);
            float p2 = __expf(acc_s[in][2] - mn1);
            float p3 = __expf(acc_s[in][3] - mn1);
            acc_s[in][0] = p0; acc_s[in][1] = p1; acc_s[in][2] = p2; acc_s[in][3] = p3;
            s0 += p0 + p1; s1 += p2 + p3;
        }
        l_r[0] = l_r[0] * al0 + s0;
        l_r[1] = l_r[1] * al1 + s1;
        m_r[0] = mn0; m_r[1] = mn1;
        #pragma unroll
        for (int nf = 0; nf < 8; nf++) {
            acc_o[nf][0] *= al0; acc_o[nf][1] *= al0;
            acc_o[nf][2] *= al1; acc_o[nf][3] *= al1;
        }

        __syncthreads();     // Kb free; Pb free (Q frags already in regs)
        if (jt < 15) loadK(jt + 1);

        // ---- store P (128 x 64) ----
        #pragma unroll
        for (int in = 0; in < 8; in++) {
            int col = in * 8 + tg * 2;
            *(float2*)&Pb[(w * 16 + g)     * FST + col] = make_float2(acc_s[in][0], acc_s[in][1]);
            *(float2*)&Pb[(w * 16 + g + 8) * FST + col] = make_float2(acc_s[in][2], acc_s[in][3]);
        }
        if (jt < 15) { CP_WAIT1(); } else { CP_WAIT0(); }  // V_jt arrived
        __syncthreads();

        // ---- O += P V (k = 64) ----
        #pragma unroll
        for (int kc2 = 0; kc2 < 8; kc2++) {
            uint32_t af[4];
            ldsm_x4(af, sP + (uint32_t)((w * 16) * FST + aoffA + kc2 * 8) * 4u);
            #pragma unroll
            for (int ip = 0; ip < 4; ip++) {
                uint32_t bf[4];
                ldsm_x4(bf, sV + (uint32_t)((ip * 16) * FST + boffB + kc2 * 8) * 4u);
                mma_tf32(acc_o[ip * 2],     af, &bf[0]);
                mma_tf32(acc_o[ip * 2 + 1], af, &bf[2]);
            }
        }
        __syncthreads();     // Vb free
        if (jt < 15) loadV(jt + 1);
    }

    // ---- finalize ----
    float l0 = l_r[0];
    l0 += __shfl_xor_sync(0xffffffffu, l0, 1);
    l0 += __shfl_xor_sync(0xffffffffu, l0, 2);
    float l1 = l_r[1];
    l1 += __shfl_xor_sync(0xffffffffu, l1, 1);
    l1 += __shfl_xor_sync(0xffffffffu, l1, 2);
    float inv0 = 1.0f / l0, inv1 = 1.0f / l1;
    float* c0 = ctx + ((size_t)bb * Ssz + mg0)     * Dsz + hh * DHsz;
    float* c1 = ctx + ((size_t)bb * Ssz + mg0 + 8) * Dsz + hh * DHsz;
    #pragma unroll
    for (int nf = 0; nf < 8; nf++) {
        int col = nf * 8 + tg * 2;
        *(float2*)&c0[col] = make_float2(acc_o[nf][0] * inv0, acc_o[nf][1] * inv0);
        *(float2*)&c1[col] = make_float2(acc_o[nf][2] * inv1, acc_o[nf][3] * inv1);
    }
}

// =============================== launch ========================================
extern "C" void kernel_launch(void* const* d_in, const int* in_sizes, int n_in,
                              void* d_out, int out_size) {
    const float* x      = (const float*)d_in[0];
    const float* ln1g   = (const float*)d_in[1];
    const float* ln1b   = (const float*)d_in[2];
    const float* dww    = (const float*)d_in[3];
    const float* dwb    = (const float*)d_in[4];
    const float* pww    = (const float*)d_in[5];
    const float* pwb    = (const float*)d_in[6];
    const float* ln2g   = (const float*)d_in[7];
    const float* ln2b   = (const float*)d_in[8];
    const float* qw     = (const float*)d_in[9];
    const float* qb     = (const float*)d_in[10];
    const float* kw     = (const float*)d_in[11];
    const float* kb     = (const float*)d_in[12];
    const float* vw     = (const float*)d_in[13];
    const float* vb     = (const float*)d_in[14];
    const float* ow     = (const float*)d_in[15];
    const float* ob     = (const float*)d_in[16];
    const float* relemb = (const float*)d_in[17];
    const float* ln3g   = (const float*)d_in[18];
    const float* ln3b   = (const float*)d_in[19];
    const float* w1     = (const float*)d_in[20];
    const float* b1     = (const float*)d_in[21];
    const float* w2     = (const float*)d_in[22];
    const float* b2     = (const float*)d_in[23];
    float* out = (float*)d_out;

    float *xn, *conv, *x1, *x2, *q, *k, *v, *vt, *ctx, *posk, *posq, *c2p, *p2c, *ff;
    int* lut;
    cudaGetSymbolAddress((void**)&xn,   g_xn);
    cudaGetSymbolAddress((void**)&conv, g_conv);
    cudaGetSymbolAddress((void**)&x1,   g_x1);
    cudaGetSymbolAddress((void**)&x2,   g_x2);
    cudaGetSymbolAddress((void**)&q,    g_q);
    cudaGetSymbolAddress((void**)&k,    g_k);
    cudaGetSymbolAddress((void**)&v,    g_v);
    cudaGetSymbolAddress((void**)&vt,   g_vt);
    cudaGetSymbolAddress((void**)&ctx,  g_ctx);
    cudaGetSymbolAddress((void**)&posk, g_posk);
    cudaGetSymbolAddress((void**)&posq, g_posq);
    cudaGetSymbolAddress((void**)&c2p,  g_c2p);
    cudaGetSymbolAddress((void**)&p2c,  g_p2c);
    cudaGetSymbolAddress((void**)&ff,   g_ff);
    cudaGetSymbolAddress((void**)&lut,  g_lut);

    static int attr_set = 0;
    if (!attr_set) {
        cudaFuncSetAttribute(flash_attn_kernel,
                             cudaFuncAttributeMaxDynamicSharedMemorySize, FA_SMEM);
        cudaFuncSetAttribute(gemm_mma_kernel<128,2,0>,
                             cudaFuncAttributeMaxDynamicSharedMemorySize, GEMM_SMEM(128));
        cudaFuncSetAttribute(gemm_mma_kernel<128,1,4>,
                             cudaFuncAttributeMaxDynamicSharedMemorySize, GEMM_SMEM(128));
        cudaFuncSetAttribute(gemm_mma_kernel<128,3,0>,
                             cudaFuncAttributeMaxDynamicSharedMemorySize, GEMM_SMEM(128));
        cudaFuncSetAttribute(gemm_pos_kernel<64>,
                             cudaFuncAttributeMaxDynamicSharedMemorySize, GEMM_SMEM(64));
        attr_set = 1;
    }

    build_lut_kernel<<<8, 256>>>(lut);

    // ---- conv block ----
    layernorm_kernel<<<NROWS, 256>>>(x, ln1g, ln1b, xn);
    dwconv_silu_kernel<<<(Bsz*Ssz*Dsz + 255) / 256, 256>>>(xn, dww, dwb, conv);
    gemm_mma_kernel<128,2,0><<<dim3(Dsz/128, NROWS/128, 1), 256, GEMM_SMEM(128)>>>(
        conv, Dsz, pww, Dsz, pwb, x, x1, Dsz, Dsz,
        nullptr, nullptr, nullptr, nullptr, nullptr, nullptr, nullptr);

    // ---- attention block ----
    layernorm_kernel<<<NROWS, 256>>>(x1, ln2g, ln2b, xn);
    gemm_mma_kernel<128,1,4><<<dim3(Dsz/128, NROWS/128, 3), 256, GEMM_SMEM(128)>>>(
        xn, Dsz, qw, Dsz, qb, nullptr, q, Dsz, Dsz,
        nullptr, kw, vw, kb, vb, k, v);
    transpose_v_kernel<<<dim3(Ssz/32, Dsz/32, Bsz), dim3(32, 8)>>>(v, vt);

    gemm_tn_small_kernel<<<dim3(Dsz/64, 1), 256>>>(relemb, Dsz, kw, Dsz, kb, posk, Dsz, Dsz);
    gemm_tn_small_kernel<<<dim3(Dsz/64, 1), 256>>>(relemb, Dsz, qw, Dsz, qb, posq, Dsz, Dsz);

    gemm_pos_kernel<64><<<dim3(1, Ssz/128, 2*Bsz*Hsz), 256, GEMM_SMEM(64)>>>(
        q, posk, c2p, k, posq, p2c);

    flash_attn_kernel<<<dim3(Ssz/128, 1, Bsz*Hsz), 256, FA_SMEM>>>(
        q, k, vt, c2p, p2c, lut, ctx);

    gemm_mma_kernel<128,2,0><<<dim3(Dsz/128, NROWS/128, 1), 256, GEMM_SMEM(128)>>>(
        ctx, Dsz, ow, Dsz, ob, x1, x2, Dsz, Dsz,
        nullptr, nullptr, nullptr, nullptr, nullptr, nullptr, nullptr);

    // ---- FFN block ----
    layernorm_kernel<<<NROWS, 256>>>(x2, ln3g, ln3b, xn);
    gemm_mma_kernel<128,3,0><<<dim3(FFsz/128, NROWS/128, 1), 256, GEMM_SMEM(128)>>>(
        xn, Dsz, w1, Dsz, b1, nullptr, ff, FFsz, Dsz,
        nullptr, nullptr, nullptr, nullptr, nullptr, nullptr, nullptr);
    gemm_mma_kernel<128,2,0><<<dim3(Dsz/128, NROWS/128, 1), 256, GEMM_SMEM(128)>>>(
        ff, FFsz, w2, FFsz, b2, x2, out, Dsz, FFsz,
        nullptr, nullptr, nullptr, nullptr, nullptr, nullptr, nullptr);
}

// round 9
// speedup vs baseline: 1.1941x; 1.0757x over previous
#include <cuda_runtime.h>
#include <math.h>
#include <stdint.h>

#define Bsz 8
#define Ssz 1024
#define Dsz 512
#define Hsz 8
#define DHsz 64
#define FFsz 1024
#define NPOS 64          // 2*SPAN
#define NROWS (Bsz*Ssz)  // 8192

// ---------------- scratch (device globals; no allocation allowed) ------------
__device__ float g_xn  [Bsz*Ssz*Dsz];
__device__ float g_conv[Bsz*Ssz*Dsz];
__device__ float g_x1  [Bsz*Ssz*Dsz];
__device__ float g_x2  [Bsz*Ssz*Dsz];
__device__ float g_q   [Bsz*Ssz*Dsz];
__device__ float g_k   [Bsz*Ssz*Dsz];
__device__ float g_v   [Bsz*Ssz*Dsz];
__device__ float g_vt  [Bsz*Ssz*Dsz];   // [B, D, S], S pre-permuted within 8-groups
__device__ float g_ctx [Bsz*Ssz*Dsz];
__device__ float g_posk[NPOS*Dsz];
__device__ float g_posq[NPOS*Dsz];
__device__ float g_c2p [Bsz*Hsz*Ssz*NPOS];
__device__ float g_p2c [Bsz*Hsz*Ssz*NPOS];
__device__ float g_ff  [Bsz*Ssz*FFsz];
__device__ int   g_lut [2*Ssz];

// ---------------- relative-position bucket LUT --------------------------------
__global__ void build_lut_kernel(int* __restrict__ lut) {
    int t = blockIdx.x * blockDim.x + threadIdx.x;
    if (t >= 2*Ssz - 1) return;
    int rel = t - (Ssz - 1);   // i - j
    const int mid = 16;        // BUCKETS/2
    int bucket;
    if (rel > -mid && rel < mid) {
        bucket = rel;
    } else {
        float absp = fabsf((float)rel);
        if (absp <= (float)mid) {
            bucket = rel;
        } else {
            float logp = ceilf(logf(absp / 16.0f) / logf(127.0f / 16.0f) * 15.0f) + 16.0f;
            bucket = (rel > 0 ? 1 : -1) * (int)logp;
        }
    }
    int idx = bucket + 32;
    idx = min(max(idx, 0), 63);
    lut[t] = idx;
}

// ---------------- LayerNorm (D=512, one block per row) ------------------------
__global__ void layernorm_kernel(const float* __restrict__ x,
                                 const float* __restrict__ g,
                                 const float* __restrict__ bb,
                                 float* __restrict__ out) {
    const float* xr = x + (size_t)blockIdx.x * Dsz;
    float* orow = out + (size_t)blockIdx.x * Dsz;
    int tid = threadIdx.x;  // 256
    float v0 = xr[tid], v1 = xr[tid + 256];
    float s = v0 + v1, ss = v0 * v0 + v1 * v1;
    __shared__ float r1[8], r2[8];
    #pragma unroll
    for (int o = 16; o; o >>= 1) {
        s  += __shfl_xor_sync(0xffffffffu, s, o);
        ss += __shfl_xor_sync(0xffffffffu, ss, o);
    }
    if ((tid & 31) == 0) { r1[tid >> 5] = s; r2[tid >> 5] = ss; }
    __syncthreads();
    float S1 = 0.f, S2 = 0.f;
    #pragma unroll
    for (int i = 0; i < 8; i++) { S1 += r1[i]; S2 += r2[i]; }
    float mean = S1 * (1.0f / Dsz);
    float var  = S2 * (1.0f / Dsz) - mean * mean;
    float rs = rsqrtf(var + 1e-5f);
    orow[tid]       = (v0 - mean) * rs * g[tid]       + bb[tid];
    orow[tid + 256] = (v1 - mean) * rs * g[tid + 256] + bb[tid + 256];
}

// ---------------- depthwise conv (K=3 along S) + bias + SiLU ------------------
__global__ void dwconv_silu_kernel(const float* __restrict__ xn,
                                   const float* __restrict__ w,
                                   const float* __restrict__ bias,
                                   float* __restrict__ out) {
    size_t idx = (size_t)blockIdx.x * blockDim.x + threadIdx.x;
    if (idx >= (size_t)Bsz * Ssz * Dsz) return;
    int d = (int)(idx % Dsz);
    int s = (int)((idx / Dsz) % Ssz);
    const float* base = xn + idx;
    float w0 = w[d * 3 + 0], w1 = w[d * 3 + 1], w2 = w[d * 3 + 2];
    float acc = bias[d] + base[0] * w1;
    if (s > 0)        acc += base[-Dsz] * w0;
    if (s < Ssz - 1)  acc += base[ Dsz] * w2;
    out[idx] = acc / (1.0f + expf(-acc));  // silu
}

// ---------------- V transpose: [B,S,D] -> [B,D,S] with j permutation -----------
// Within each 8-column group of S: j even -> slot j/2, j odd -> slot 4 + j/2.
// This matches the tf32 mma A-fragment k-slot order so P can stay in registers.
__global__ void transpose_v_kernel(const float* __restrict__ v, float* __restrict__ vt) {
    __shared__ float tile[32][33];
    int b = blockIdx.z;
    int s0 = blockIdx.x * 32, d0 = blockIdx.y * 32;
    int tx = threadIdx.x, ty = threadIdx.y;  // 32 x 8
    #pragma unroll
    for (int j = 0; j < 32; j += 8)
        tile[ty + j][tx] = v[((size_t)b * Ssz + s0 + ty + j) * Dsz + d0 + tx];
    __syncthreads();
    int sl = tx & 7;
    int sp = (s0 + (tx & ~7)) | ((sl & 1) ? (4 + (sl >> 1)) : (sl >> 1));
    #pragma unroll
    for (int j = 0; j < 32; j += 8)
        vt[((size_t)b * Dsz + d0 + ty + j) * Ssz + sp] = tile[tx][ty + j];
}

// ---------------- mma.tf32 + ldmatrix helpers ----------------------------------
__device__ __forceinline__ void mma_tf32(float c[4], const uint32_t a[4], const uint32_t b[2]) {
    asm volatile(
        "mma.sync.aligned.m16n8k8.row.col.f32.tf32.tf32.f32 "
        "{%0,%1,%2,%3}, {%4,%5,%6,%7}, {%8,%9}, {%0,%1,%2,%3};"
        : "+f"(c[0]), "+f"(c[1]), "+f"(c[2]), "+f"(c[3])
        : "r"(a[0]), "r"(a[1]), "r"(a[2]), "r"(a[3]), "r"(b[0]), "r"(b[1]));
}

__device__ __forceinline__ void ldsm_x4(uint32_t r[4], uint32_t addr) {
    asm volatile("ldmatrix.sync.aligned.m8n8.x4.shared.b16 {%0,%1,%2,%3}, [%4];"
                 : "=r"(r[0]), "=r"(r[1]), "=r"(r[2]), "=r"(r[3]) : "r"(addr));
}

#define CP_ASYNC16(dst_u32, src_ptr) \
    asm volatile("cp.async.ca.shared.global [%0], [%1], 16;" :: "r"(dst_u32), "l"(src_ptr))
#define CP_COMMIT() asm volatile("cp.async.commit_group;")
#define CP_WAIT2()  asm volatile("cp.async.wait_group 2;")
#define CP_WAIT1()  asm volatile("cp.async.wait_group 1;")
#define CP_WAIT0()  asm volatile("cp.async.wait_group 0;")

// ---------------- tensor-core TN GEMM (128xCN tiles, 4-stage, 1 barrier/iter) --
// C[m,n] = sum_k A[m,k] * W[n,k]
// EPI: 0 none, 1 +bias, 2 +bias+res, 3 silu(+bias)
// MODE: 0 plain, 4 qkv-merged (z selects {qw,kw,vw})
#define SSTRIDE 20
#define NSTAGE 4
#define GEMM_SMEM(CNv) (NSTAGE * (128 + (CNv)) * SSTRIDE * 4)

template<int CN, int EPI, int MODE>
__global__ void __launch_bounds__(256, 2) gemm_mma_kernel(
    const float* __restrict__ A0, int lda,
    const float* __restrict__ W0, int ldw,
    const float* __restrict__ bias0, const float* __restrict__ res,
    float* __restrict__ C0, int ldc, int K,
    const float* __restrict__ Aa, const float* __restrict__ Wa,
    const float* __restrict__ Wb2, const float* __restrict__ ba,
    const float* __restrict__ bb2, float* __restrict__ Ca, float* __restrict__ Cb)
{
    constexpr int NWN = CN / 32;     // warps along N
    constexpr int NWM = 8 / NWN;     // warps along M
    constexpr int MT  = 8 / NWM;     // m16 tiles per warp

    extern __shared__ float smem[];
    float* As = smem;
    float* Ws = smem + NSTAGE * 128 * SSTRIDE;

    const int tid  = threadIdx.x;
    const int wid  = tid >> 5, lane = tid & 31;
    const int g    = lane >> 2, tg = lane & 3;
    const int wm   = wid % NWM, wn = wid / NWM;

    const int z = blockIdx.z;
    const float* A = A0; const float* W = W0; float* C = C0;
    const float* bias = bias0;
    if (MODE == 4) {
        W    = (z == 0) ? W0 : (z == 1 ? Wa : Wb2);
        bias = (z == 0) ? bias0 : (z == 1 ? ba : bb2);
        C    = (z == 0) ? C0 : (z == 1 ? Ca : Cb);
    }

    const int m_cta = blockIdx.y * 128, n_cta = blockIdx.x * CN;

    const uint32_t sA = (uint32_t)__cvta_generic_to_shared(As);
    const uint32_t sW = (uint32_t)__cvta_generic_to_shared(Ws);

    const int qd = (tid & 3) * 4;
    const int rr = tid >> 2;

    auto fetch = [&](int t, int buf) {
        int k0 = t * 16;
        #pragma unroll
        for (int r = 0; r < 2; r++) {
            int row = rr + 64 * r;
            uint32_t d = sA + (uint32_t)(buf * 128 * SSTRIDE + row * SSTRIDE + qd) * 4u;
            CP_ASYNC16(d, A + (size_t)(m_cta + row) * lda + k0 + qd);
        }
        #pragma unroll
        for (int r = 0; r < CN / 64; r++) {
            int row = rr + 64 * r;
            uint32_t d = sW + (uint32_t)(buf * CN * SSTRIDE + row * SSTRIDE + qd) * 4u;
            CP_ASYNC16(d, W + (size_t)(n_cta + row) * ldw + k0 + qd);
        }
        CP_COMMIT();
    };

    const int lq = lane >> 3, lr = lane & 7;
    const int aoff = ((lq & 1) * 8 + lr) * SSTRIDE + (lq >> 1) * 4;
    const int boff = ((lq >> 1) * 8 + lr) * SSTRIDE + (lq & 1) * 4;

    float acc[MT][4][4] = {};

    const int T = K / 16;
    fetch(0, 0);
    fetch(1, 1);
    if (T > 2) fetch(2, 2);
    for (int it = 0; it < T; it++) {
        const int buf = it & (NSTAGE - 1);
        if (it < T - 2)       { CP_WAIT2(); }
        else if (it == T - 2) { CP_WAIT1(); }
        else                  { CP_WAIT0(); }
        __syncthreads();
        if (it + 3 < T) fetch(it + 3, (it + 3) & (NSTAGE - 1));

        const uint32_t bA = sA + (uint32_t)(buf * 128 * SSTRIDE) * 4u;
        const uint32_t bW = sW + (uint32_t)(buf * CN  * SSTRIDE) * 4u;
        #pragma unroll
        for (int ks = 0; ks < 2; ks++) {
            const int kk = ks * 8;
            uint32_t af[MT][4];
            #pragma unroll
            for (int im = 0; im < MT; im++)
                ldsm_x4(af[im], bA + (uint32_t)((wm * MT * 16 + im * 16) * SSTRIDE + aoff + kk) * 4u);
            uint32_t bf[2][4];
            #pragma unroll
            for (int ip = 0; ip < 2; ip++)
                ldsm_x4(bf[ip], bW + (uint32_t)((wn * 32 + ip * 16) * SSTRIDE + boff + kk) * 4u);
            #pragma unroll
            for (int im = 0; im < MT; im++)
                #pragma unroll
                for (int in = 0; in < 4; in++)
                    mma_tf32(acc[im][in], af[im], &bf[in >> 1][(in & 1) * 2]);
        }
    }

    #pragma unroll
    for (int im = 0; im < MT; im++) {
        int mrow0 = m_cta + wm * MT * 16 + im * 16 + g;
        #pragma unroll
        for (int in = 0; in < 4; in++) {
            int ncol0 = n_cta + wn * 32 + in * 8 + tg * 2;
            #pragma unroll
            for (int e = 0; e < 4; e++) {
                int m = mrow0 + ((e >= 2) ? 8 : 0);
                int n = ncol0 + (e & 1);
                float vv = acc[im][in][e];
                if (EPI == 1 || EPI == 2 || EPI == 3) vv += bias[n];
                if (EPI == 2) vv += res[(size_t)m * ldc + n];
                if (EPI == 3) vv = vv / (1.0f + expf(-vv));
                C[(size_t)m * ldc + n] = vv;
            }
        }
    }
}

// ---------------- mma GEMM for pos projections (small N=64, K=64) --------------
template<int CN>
__global__ void __launch_bounds__(256, 2) gemm_pos_kernel(
    const float* __restrict__ A0,
    const float* __restrict__ W0,
    float* __restrict__ C0,
    const float* __restrict__ Aa, const float* __restrict__ Wa,
    float* __restrict__ Ca)
{
    constexpr int NWN = CN / 32;
    constexpr int NWM = 8 / NWN;
    constexpr int MT  = 8 / NWM;
    const int K = DHsz;

    extern __shared__ float smem[];
    float* As = smem;
    float* Ws = smem + NSTAGE * 128 * SSTRIDE;

    const int tid  = threadIdx.x;
    const int wid  = tid >> 5, lane = tid & 31;
    const int g    = lane >> 2, tg = lane & 3;
    const int wm   = wid % NWM, wn = wid / NWM;

    int zz = blockIdx.z & 63, sel = blockIdx.z >> 6;
    int bb = zz >> 3, hh = zz & 7;
    const float* A = (sel ? Aa : A0) + (size_t)bb * Ssz * Dsz + hh * DHsz;
    const float* W = (sel ? Wa : W0) + hh * DHsz;
    float* C = (sel ? Ca : C0) + (size_t)zz * Ssz * NPOS;

    const int m_cta = blockIdx.y * 128;

    const uint32_t sA = (uint32_t)__cvta_generic_to_shared(As);
    const uint32_t sW = (uint32_t)__cvta_generic_to_shared(Ws);
    const int qd = (tid & 3) * 4;
    const int rr = tid >> 2;

    auto fetch = [&](int t, int buf) {
        int k0 = t * 16;
        #pragma unroll
        for (int r = 0; r < 2; r++) {
            int row = rr + 64 * r;
            CP_ASYNC16(sA + (uint32_t)(buf * 128 * SSTRIDE + row * SSTRIDE + qd) * 4u,
                       A + (size_t)(m_cta + row) * Dsz + k0 + qd);
        }
        if (rr < CN)
            CP_ASYNC16(sW + (uint32_t)(buf * CN * SSTRIDE + rr * SSTRIDE + qd) * 4u,
                       W + (size_t)rr * Dsz + k0 + qd);
        CP_COMMIT();
    };

    const int lq = lane >> 3, lr = lane & 7;
    const int aoff = ((lq & 1) * 8 + lr) * SSTRIDE + (lq >> 1) * 4;
    const int boff = ((lq >> 1) * 8 + lr) * SSTRIDE + (lq & 1) * 4;

    float acc[MT][4][4] = {};
    const int T = K / 16;   // 4
    fetch(0, 0); fetch(1, 1); if (T > 2) fetch(2, 2);
    for (int it = 0; it < T; it++) {
        const int buf = it & (NSTAGE - 1);
        if (it < T - 2)       { CP_WAIT2(); }
        else if (it == T - 2) { CP_WAIT1(); }
        else                  { CP_WAIT0(); }
        __syncthreads();
        if (it + 3 < T) fetch(it + 3, (it + 3) & (NSTAGE - 1));
        const uint32_t bA = sA + (uint32_t)(buf * 128 * SSTRIDE) * 4u;
        const uint32_t bW = sW + (uint32_t)(buf * CN  * SSTRIDE) * 4u;
        #pragma unroll
        for (int ks = 0; ks < 2; ks++) {
            const int kk = ks * 8;
            uint32_t af[MT][4];
            #pragma unroll
            for (int im = 0; im < MT; im++)
                ldsm_x4(af[im], bA + (uint32_t)((wm * MT * 16 + im * 16) * SSTRIDE + aoff + kk) * 4u);
            uint32_t bf[2][4];
            #pragma unroll
            for (int ip = 0; ip < 2; ip++)
                ldsm_x4(bf[ip], bW + (uint32_t)((wn * 32 + ip * 16) * SSTRIDE + boff + kk) * 4u);
            #pragma unroll
            for (int im = 0; im < MT; im++)
                #pragma unroll
                for (int in = 0; in < 4; in++)
                    mma_tf32(acc[im][in], af[im], &bf[in >> 1][(in & 1) * 2]);
        }
    }

    #pragma unroll
    for (int im = 0; im < MT; im++) {
        int mrow0 = m_cta + wm * MT * 16 + im * 16 + g;
        #pragma unroll
        for (int in = 0; in < 4; in++) {
            int ncol0 = wn * 32 + in * 8 + tg * 2;
            #pragma unroll
            for (int e = 0; e < 4; e++) {
                int m = mrow0 + ((e >= 2) ? 8 : 0);
                int nn = ncol0 + (e & 1);
                C[(size_t)m * NPOS + nn] = acc[im][in][e];
            }
        }
    }
}

// ---------------- small SIMT GEMM (pos-emb projections, M=64, merged) ----------
#define TK 16
#define TPAD 68
__global__ void gemm_tn_small_kernel(const float* __restrict__ A, int lda,
                                     const float* __restrict__ W0, int ldw,
                                     const float* __restrict__ b0,
                                     float* __restrict__ C0,
                                     const float* __restrict__ W1,
                                     const float* __restrict__ b1,
                                     float* __restrict__ C1, int ldc, int Kd) {
    const float* W   = blockIdx.z ? W1 : W0;
    const float* bias= blockIdx.z ? b1 : b0;
    float* C         = blockIdx.z ? C1 : C0;
    int m0 = blockIdx.y * 64, n0 = blockIdx.x * 64;
    __shared__ float As[TK][TPAD];
    __shared__ float Ws2[TK][TPAD];
    const int tid = threadIdx.x;
    const int tx = tid & 15, ty = tid >> 4;
    const int lk = tid & 15, lm = tid >> 4;
    float acc[4][4] = {};
    for (int k0 = 0; k0 < Kd; k0 += TK) {
        #pragma unroll
        for (int r = 0; r < 4; r++) {
            As[lk][lm + 16 * r]  = A[(size_t)(m0 + lm + 16 * r) * lda + k0 + lk];
            Ws2[lk][lm + 16 * r] = W[(size_t)(n0 + lm + 16 * r) * ldw + k0 + lk];
        }
        __syncthreads();
        #pragma unroll
        for (int kk = 0; kk < TK; kk++) {
            float4 a = *(const float4*)&As[kk][ty * 4];
            float4 b = *(const float4*)&Ws2[kk][tx * 4];
            float av[4] = {a.x, a.y, a.z, a.w};
            float bv[4] = {b.x, b.y, b.z, b.w};
            #pragma unroll
            for (int i = 0; i < 4; i++)
                #pragma unroll
                for (int j = 0; j < 4; j++)
                    acc[i][j] += av[i] * bv[j];
        }
        __syncthreads();
    }
    #pragma unroll
    for (int i = 0; i < 4; i++) {
        int m = m0 + ty * 4 + i;
        #pragma unroll
        for (int j = 0; j < 4; j++) {
            int n = n0 + tx * 4 + j;
            C[(size_t)m * ldc + n] = acc[i][j] + bias[n];
        }
    }
}

// =========================== fused flash attention =============================
// One CTA per (z = b*H+h, i-tile of 128). 8 warps; warp w owns rows [w*16, w*16+16).
// j-tile 64, KV fused double-buffer (1 cp.async group + 1 barrier per iter),
// P kept in registers (V pre-permuted so acc_s bit-casts into A-fragments).
#define FST 68
#define FA_K(buf) ((buf) * 64 * FST)
#define FA_V(buf) (2 * 64 * FST + (buf) * 64 * FST)
#define FA_Q      (4 * 64 * FST)
#define FA_LUT    (4 * 64 * FST + 128 * FST)
#define FA_SMEM   ((4*64*FST + 128*FST + 2048) * 4)

__global__ void __launch_bounds__(256, 2) flash_attn_kernel(
    const float* __restrict__ qg, const float* __restrict__ kg,
    const float* __restrict__ vt,
    const float* __restrict__ c2p, const float* __restrict__ p2c,
    const int* __restrict__ lut, float* __restrict__ ctx)
{
    extern __shared__ float sm[];
    int* lut_s = (int*)(sm + FA_LUT);

    const int tid = threadIdx.x, w = tid >> 5, lane = tid & 31;
    const int g = lane >> 2, tg = lane & 3;
    const int z = blockIdx.z, bb = z >> 3, hh = z & 7;
    const int i0 = blockIdx.x * 128;

    const float* c2pz = c2p + (size_t)z * Ssz * NPOS;
    const float* p2cz = p2c + (size_t)z * Ssz * NPOS;

    const uint32_t sb = (uint32_t)__cvta_generic_to_shared(sm);

    // lut -> smem (published by the prologue __syncthreads)
    #pragma unroll
    for (int t = 0; t < 8; t++) {
        int idx = tid + 256 * t;
        if (idx < 2 * Ssz - 1) lut_s[idx] = lut[idx];
    }

    // fused K+V tile load: one cp.async group per j-tile
    auto loadKV = [&](int jt, int buf) {
        int j0 = jt * 64;
        #pragma unroll
        for (int c = 0; c < 4; c++) {       // K: 64 j-rows x 64 d
            int id = tid * 4 + c;
            int row = id >> 4, fcol = (id & 15) * 4;
            CP_ASYNC16(sb + (uint32_t)(FA_K(buf) + row * FST + fcol) * 4u,
                       kg + ((size_t)bb * Ssz + j0 + row) * Dsz + hh * DHsz + fcol);
        }
        #pragma unroll
        for (int c = 0; c < 4; c++) {       // V: 64 d-rows x 64 j (pre-permuted)
            int id = tid * 4 + c;
            int row = id >> 4, fcol = (id & 15) * 4;
            CP_ASYNC16(sb + (uint32_t)(FA_V(buf) + row * FST + fcol) * 4u,
                       vt + ((size_t)bb * Dsz + hh * DHsz + row) * Ssz + j0 + fcol);
        }
        CP_COMMIT();
    };

    // prologue: Q (group 0), KV0 (group 1)
    #pragma unroll
    for (int c = 0; c < 8; c++) {
        int id = tid * 8 + c;
        int row = id >> 4, fcol = (id & 15) * 4;
        CP_ASYNC16(sb + (uint32_t)(FA_Q + row * FST + fcol) * 4u,
                   qg + ((size_t)bb * Ssz + i0 + row) * Dsz + hh * DHsz + fcol);
    }
    CP_COMMIT();
    loadKV(0, 0);

    CP_WAIT1();          // Q resident (KV0 may pend)
    __syncthreads();     // publishes Q + lut_s

    const int lq = lane >> 3, lr = lane & 7;
    const int aoffA = ((lq & 1) * 8 + lr) * FST + (lq >> 1) * 4;   // A frags (Q)
    const int boffB = ((lq >> 1) * 8 + lr) * FST + (lq & 1) * 4;   // B frags (K/V)

    uint32_t qf[8][4];
    #pragma unroll
    for (int kc = 0; kc < 8; kc++)
        ldsm_x4(qf[kc], sb + (uint32_t)(FA_Q + (w * 16) * FST + aoffA + kc * 8) * 4u);

    float acc_o[8][4] = {};
    float m_r[2] = {-1e30f, -1e30f};
    float l_r[2] = {0.f, 0.f};
    const float SCALE = 0.07216878364870323f;  // 1/sqrt(64*3)
    const int mg0 = i0 + w * 16 + g;

    for (int jt = 0; jt < 16; jt++) {
        const int buf = jt & 1;
        const int j0 = jt * 64;
        CP_WAIT0();          // KV_jt resident (sole in-flight group)
        __syncthreads();     // + all warps done with prior iteration's gemms
        if (jt < 15) loadKV(jt + 1, buf ^ 1);

        // ---- S = Q K^T (64 cols) ----
        float acc_s[8][4] = {};
        #pragma unroll
        for (int kc = 0; kc < 8; kc++) {
            #pragma unroll
            for (int ip = 0; ip < 4; ip++) {
                uint32_t bf[4];
                ldsm_x4(bf, sb + (uint32_t)(FA_K(buf) + (ip * 16) * FST + boffB + kc * 8) * 4u);
                mma_tf32(acc_s[ip * 2],     qf[kc], &bf[0]);
                mma_tf32(acc_s[ip * 2 + 1], qf[kc], &bf[2]);
            }
        }

        // ---- bias + online softmax ----
        float mx0 = -1e30f, mx1 = -1e30f;
        #pragma unroll
        for (int in = 0; in < 8; in++) {
            int nbase = j0 + in * 8 + tg * 2;
            #pragma unroll
            for (int e = 0; e < 4; e++) {
                int m = mg0 + ((e >= 2) ? 8 : 0);
                int n = nbase + (e & 1);
                int idx = lut_s[m - n + (Ssz - 1)];
                float vv = (acc_s[in][e] + __ldg(&c2pz[(size_t)m * NPOS + idx])
                                         + __ldg(&p2cz[(size_t)n * NPOS + idx])) * SCALE;
                acc_s[in][e] = vv;
                if (e < 2) mx0 = fmaxf(mx0, vv); else mx1 = fmaxf(mx1, vv);
            }
        }
        mx0 = fmaxf(mx0, __shfl_xor_sync(0xffffffffu, mx0, 1));
        mx0 = fmaxf(mx0, __shfl_xor_sync(0xffffffffu, mx0, 2));
        mx1 = fmaxf(mx1, __shfl_xor_sync(0xffffffffu, mx1, 1));
        mx1 = fmaxf(mx1, __shfl_xor_sync(0xffffffffu, mx1, 2));
        float mn0 = fmaxf(m_r[0], mx0), mn1 = fmaxf(m_r[1], mx1);
        float al0 = __expf(m_r[0] - mn0), al1 = __expf(m_r[1] - mn1);
        float s0 = 0.f, s1 = 0.f;
        #pragma unroll
        for (int in = 0; in < 8; in++) {
            float p0 = __expf(acc_s[in][0] - mn0);
            float p1 = __expf(acc_s[in][1] - mn0);
            float p2 = __expf(acc_s[in][2] - mn1);
            float p3 = __expf(acc_s[in][3] - mn1);
            acc_s[in][0] = p0; acc_s[in][1] = p1; acc_s[in][2] = p2; acc_s[in][3] = p3;
            s0 += p0 + p1; s1 += p2 + p3;
        }
        l_r[0] = l_r[0] * al0 + s0;
        l_r[1] = l_r[1] * al1 + s1;
        m_r[0] = mn0; m_r[1] = mn1;
        #pragma unroll
        for (int nf = 0; nf < 8; nf++) {
            acc_o[nf][0] *= al0; acc_o[nf][1] *= al0;
            acc_o[nf][2] *= al1; acc_o[nf][3] *= al1;
        }

        // ---- O += P V : P from registers (V columns pre-permuted to match) ----
        #pragma unroll
        for (int kc2 = 0; kc2 < 8; kc2++) {
            uint32_t af[4];
            af[0] = __float_as_uint(acc_s[kc2][0]);   // (row g,   slot tg)   = P(g,  2tg)
            af[1] = __float_as_uint(acc_s[kc2][2]);   // (row g+8, slot tg)   = P(g+8,2tg)
            af[2] = __float_as_uint(acc_s[kc2][1]);   // (row g,   slot tg+4) = P(g,  2tg+1)
            af[3] = __float_as_uint(acc_s[kc2][3]);   // (row g+8, slot tg+4) = P(g+8,2tg+1)
            #pragma unroll
            for (int ip = 0; ip < 4; ip++) {
                uint32_t bf[4];
                ldsm_x4(bf, sb + (uint32_t)(FA_V(buf) + (ip * 16) * FST + boffB + kc2 * 8) * 4u);
                mma_tf32(acc_o[ip * 2],     af, &bf[0]);
                mma_tf32(acc_o[ip * 2 + 1], af, &bf[2]);
            }
        }
    }

    // ---- finalize ----
    float l0 = l_r[0];
    l0 += __shfl_xor_sync(0xffffffffu, l0, 1);
    l0 += __shfl_xor_sync(0xffffffffu, l0, 2);
    float l1 = l_r[1];
    l1 += __shfl_xor_sync(0xffffffffu, l1, 1);
    l1 += __shfl_xor_sync(0xffffffffu, l1, 2);
    float inv0 = 1.0f / l0, inv1 = 1.0f / l1;
    float* c0 = ctx + ((size_t)bb * Ssz + mg0)     * Dsz + hh * DHsz;
    float* c1 = ctx + ((size_t)bb * Ssz + mg0 + 8) * Dsz + hh * DHsz;
    #pragma unroll
    for (int nf = 0; nf < 8; nf++) {
        int col = nf * 8 + tg * 2;
        *(float2*)&c0[col] = make_float2(acc_o[nf][0] * inv0, acc_o[nf][1] * inv0);
        *(float2*)&c1[col] = make_float2(acc_o[nf][2] * inv1, acc_o[nf][3] * inv1);
    }
}

// =============================== launch ========================================
extern "C" void kernel_launch(void* const* d_in, const int* in_sizes, int n_in,
                              void* d_out, int out_size) {
    const float* x      = (const float*)d_in[0];
    const float* ln1g   = (const float*)d_in[1];
    const float* ln1b   = (const float*)d_in[2];
    const float* dww    = (const float*)d_in[3];
    const float* dwb    = (const float*)d_in[4];
    const float* pww    = (const float*)d_in[5];
    const float* pwb    = (const float*)d_in[6];
    const float* ln2g   = (const float*)d_in[7];
    const float* ln2b   = (const float*)d_in[8];
    const float* qw     = (const float*)d_in[9];
    const float* qb     = (const float*)d_in[10];
    const float* kw     = (const float*)d_in[11];
    const float* kb     = (const float*)d_in[12];
    const float* vw     = (const float*)d_in[13];
    const float* vb     = (const float*)d_in[14];
    const float* ow     = (const float*)d_in[15];
    const float* ob     = (const float*)d_in[16];
    const float* relemb = (const float*)d_in[17];
    const float* ln3g   = (const float*)d_in[18];
    const float* ln3b   = (const float*)d_in[19];
    const float* w1     = (const float*)d_in[20];
    const float* b1     = (const float*)d_in[21];
    const float* w2     = (const float*)d_in[22];
    const float* b2     = (const float*)d_in[23];
    float* out = (float*)d_out;

    float *xn, *conv, *x1, *x2, *q, *k, *v, *vt, *ctx, *posk, *posq, *c2p, *p2c, *ff;
    int* lut;
    cudaGetSymbolAddress((void**)&xn,   g_xn);
    cudaGetSymbolAddress((void**)&conv, g_conv);
    cudaGetSymbolAddress((void**)&x1,   g_x1);
    cudaGetSymbolAddress((void**)&x2,   g_x2);
    cudaGetSymbolAddress((void**)&q,    g_q);
    cudaGetSymbolAddress((void**)&k,    g_k);
    cudaGetSymbolAddress((void**)&v,    g_v);
    cudaGetSymbolAddress((void**)&vt,   g_vt);
    cudaGetSymbolAddress((void**)&ctx,  g_ctx);
    cudaGetSymbolAddress((void**)&posk, g_posk);
    cudaGetSymbolAddress((void**)&posq, g_posq);
    cudaGetSymbolAddress((void**)&c2p,  g_c2p);
    cudaGetSymbolAddress((void**)&p2c,  g_p2c);
    cudaGetSymbolAddress((void**)&ff,   g_ff);
    cudaGetSymbolAddress((void**)&lut,  g_lut);

    static int attr_set = 0;
    if (!attr_set) {
        cudaFuncSetAttribute(flash_attn_kernel,
                             cudaFuncAttributeMaxDynamicSharedMemorySize, FA_SMEM);
        cudaFuncSetAttribute(gemm_mma_kernel<128,2,0>,
                             cudaFuncAttributeMaxDynamicSharedMemorySize, GEMM_SMEM(128));
        cudaFuncSetAttribute(gemm_mma_kernel<128,1,4>,
                             cudaFuncAttributeMaxDynamicSharedMemorySize, GEMM_SMEM(128));
        cudaFuncSetAttribute(gemm_mma_kernel<128,3,0>,
                             cudaFuncAttributeMaxDynamicSharedMemorySize, GEMM_SMEM(128));
        cudaFuncSetAttribute(gemm_pos_kernel<64>,
                             cudaFuncAttributeMaxDynamicSharedMemorySize, GEMM_SMEM(64));
        attr_set = 1;
    }

    build_lut_kernel<<<8, 256>>>(lut);

    // ---- conv block ----
    layernorm_kernel<<<NROWS, 256>>>(x, ln1g, ln1b, xn);
    dwconv_silu_kernel<<<(Bsz*Ssz*Dsz + 255) / 256, 256>>>(xn, dww, dwb, conv);
    gemm_mma_kernel<128,2,0><<<dim3(Dsz/128, NROWS/128, 1), 256, GEMM_SMEM(128)>>>(
        conv, Dsz, pww, Dsz, pwb, x, x1, Dsz, Dsz,
        nullptr, nullptr, nullptr, nullptr, nullptr, nullptr, nullptr);

    // ---- attention block ----
    layernorm_kernel<<<NROWS, 256>>>(x1, ln2g, ln2b, xn);
    gemm_mma_kernel<128,1,4><<<dim3(Dsz/128, NROWS/128, 3), 256, GEMM_SMEM(128)>>>(
        xn, Dsz, qw, Dsz, qb, nullptr, q, Dsz, Dsz,
        nullptr, kw, vw, kb, vb, k, v);
    transpose_v_kernel<<<dim3(Ssz/32, Dsz/32, Bsz), dim3(32, 8)>>>(v, vt);

    // merged pos-emb projections (z: 0 -> posk via kw, 1 -> posq via qw)
    gemm_tn_small_kernel<<<dim3(Dsz/64, 1, 2), 256>>>(
        relemb, Dsz, kw, Dsz, kb, posk, qw, qb, posq, Dsz, Dsz);

    gemm_pos_kernel<64><<<dim3(1, Ssz/128, 2*Bsz*Hsz), 256, GEMM_SMEM(64)>>>(
        q, posk, c2p, k, posq, p2c);

    flash_attn_kernel<<<dim3(Ssz/128, 1, Bsz*Hsz), 256, FA_SMEM>>>(
        q, k, vt, c2p, p2c, lut, ctx);

    gemm_mma_kernel<128,2,0><<<dim3(Dsz/128, NROWS/128, 1), 256, GEMM_SMEM(128)>>>(
        ctx, Dsz, ow, Dsz, ob, x1, x2, Dsz, Dsz,
        nullptr, nullptr, nullptr, nullptr, nullptr, nullptr, nullptr);

    // ---- FFN block ----
    layernorm_kernel<<<NROWS, 256>>>(x2, ln3g, ln3b, xn);
    gemm_mma_kernel<128,3,0><<<dim3(FFsz/128, NROWS/128, 1), 256, GEMM_SMEM(128)>>>(
        xn, Dsz, w1, Dsz, b1, nullptr, ff, FFsz, Dsz,
        nullptr, nullptr, nullptr, nullptr, nullptr, nullptr, nullptr);
    gemm_mma_kernel<128,2,0><<<dim3(Dsz/128, NROWS/128, 1), 256, GEMM_SMEM(128)>>>(
        ff, FFsz, w2, FFsz, b2, x2, out, Dsz, FFsz,
        nullptr, nullptr, nullptr, nullptr, nullptr, nullptr, nullptr);
}